// round 10
// baseline (speedup 1.0000x reference)
#include <cuda_runtime.h>
#include <math.h>
#include <stdint.h>

#define NB   2
#define SEQ  1024
#define EMB  1024
#define NHD  16
#define HDD  64
#define NROWS (NB*SEQ)      // 2048

// ---------------- scratch (device globals) ----------------------------------
__device__ float g_cvt[12*1024*1024];   // 48MB: 8 weights (1M ea) + xt(2M) + ctxt(2M)
__device__ float g_Qh [NB*NHD*SEQ*HDD]; // [bh][i][d]
__device__ float g_Kt [NB*NHD*HDD*SEQ]; // [bh][d][j]  (transposed K)
__device__ float g_Vh [NB*NHD*SEQ*HDD]; // [bh][j][o]
__device__ float g_S  [NB*NHD*SEQ*SEQ]; // 128MB scores/probs
__device__ float g_tmp[NROWS*EMB];
__device__ float g_x1 [NROWS*EMB];
__device__ float g_x2 [NROWS*EMB];
__device__ float g_x1t[NROWS*EMB];
__device__ float g_x2t[NROWS*EMB];
__device__ float g_hid[NROWS*EMB];

__device__ __forceinline__ float cvt_tf32(float x) {
    uint32_t u;
    asm("cvt.rna.tf32.f32 %0, %1;" : "=r"(u) : "f"(x));
    return __uint_as_float(u);
}

__device__ __forceinline__ void mma_tf32(float* d,
                                         const uint32_t* a, const uint32_t* b) {
    asm volatile(
        "mma.sync.aligned.m16n8k8.row.col.f32.tf32.tf32.f32 "
        "{%0,%1,%2,%3}, {%4,%5,%6,%7}, {%8,%9}, {%0,%1,%2,%3};"
        : "+f"(d[0]), "+f"(d[1]), "+f"(d[2]), "+f"(d[3])
        : "r"(a[0]), "r"(a[1]), "r"(a[2]), "r"(a[3]), "r"(b[0]), "r"(b[1]));
}

// ---------------------------------------------------------------------------
// One-shot tf32 rounding pass: 8 weight matrices + x + ctx -> g_cvt.
// ---------------------------------------------------------------------------
struct CvtPtrs { const float4* p[12]; };

__global__ void cvt_all_k(CvtPtrs ptrs, float4* __restrict__ dst)
{
    int i = blockIdx.x * blockDim.x + threadIdx.x;
    if (i >= 12 * 262144) return;
    int seg = i >> 18;
    int off = i & 0x3FFFF;
    float4 v = ptrs.p[seg][off];
    float4 w;
    w.x = cvt_tf32(v.x); w.y = cvt_tf32(v.y);
    w.z = cvt_tf32(v.z); w.w = cvt_tf32(v.w);
    dst[i] = w;
}

// ---------------------------------------------------------------------------
// tf32 GEMM, 128x64x32 tile, 256 threads = 8 warps (4 rows x 2 cols),
// warp tile 32x32 (MF=2, NF=4), 4-stage cp.async pipeline.
// A: [M,K] row-major, tf32-rounded.  B: [K,N] row-major, tf32-rounded.
// MODE 0: C[r*1024+c] = acc + bias[c]                       (fp32)
// MODE 1: relu(acc+bias) rounded to tf32                    (hid)
// MODE 2: head-scatter rounded: Qh/Vh[((b*16+h)*1024+i)*64+d]
// MODE 3: scores: C[z*1M + r*1024 + c] = acc*0.125          (fp32)
// MODE 4: pv interleave: C[(b*1024+r)*1024 + c*16 + h]      (fp32)
// MODE 5: K-transpose scatter rounded: Kt[((b*16+h)*64+d)*1024+i]
// ---------------------------------------------------------------------------
template<int MODE>
__global__ void __launch_bounds__(256, 2)
tf32gemm3(const float* __restrict__ A, const float* __restrict__ Bg,
          const float* __restrict__ bias, float* __restrict__ C,
          int K, int lda, int ldb, size_t astride, size_t bstride)
{
    constexpr int BM = 128, BN = 64, BK = 32, STG = 4;
    constexpr int AROW = BK + 4;       // 36 floats
    constexpr int BROW = BN + 8;       // 72 floats
    constexpr int ASTGF = BM * AROW;   // 4608 floats
    constexpr int BSTGF = BK * BROW;   // 2304 floats

    extern __shared__ float sm[];
    float* As = sm;
    float* Bs = sm + STG * ASTGF;
    const uint32_t sAb = (uint32_t)__cvta_generic_to_shared(As);
    const uint32_t sBb = (uint32_t)__cvta_generic_to_shared(Bs);

    const int tid  = threadIdx.x;
    const int lane = tid & 31;
    const int wid  = tid >> 5;
    const int g    = lane >> 2;
    const int tig  = lane & 3;
    const int wrow = wid >> 1;      // 0..3  (M direction, 32 rows each)
    const int wcol = wid & 1;       // 0..1  (N direction, 32 cols each)

    const int z  = blockIdx.z;
    const int m0 = blockIdx.y * BM;
    const int n0 = blockIdx.x * BN;
    const float* Ab = A  + (size_t)z * astride;
    const float* Bb = Bg + (size_t)z * bstride;

    float acc[2][4][4];
    #pragma unroll
    for (int i = 0; i < 2; i++)
        #pragma unroll
        for (int j = 0; j < 4; j++)
            #pragma unroll
            for (int q = 0; q < 4; q++) acc[i][j][q] = 0.f;

    auto load_stage = [&](int s, int k0) {
        #pragma unroll
        for (int i = 0; i < 4; i++) {             // A: 128 rows x 8 float4
            int q   = tid + i * 256;
            int row = q >> 3, kq = (q & 7) << 2;
            const float* src = Ab + (size_t)(m0 + row) * lda + k0 + kq;
            uint32_t dst = sAb + (uint32_t)((s * ASTGF + row * AROW + kq) * 4);
            asm volatile("cp.async.cg.shared.global [%0], [%1], 16;"
                         :: "r"(dst), "l"(src));
        }
        #pragma unroll
        for (int i = 0; i < 2; i++) {             // B: 32 rows x 16 float4
            int q   = tid + i * 256;
            int row = q >> 4, nq = (q & 15) << 2;
            const float* src = Bb + (size_t)(k0 + row) * ldb + n0 + nq;
            uint32_t dst = sBb + (uint32_t)((s * BSTGF + row * BROW + nq) * 4);
            asm volatile("cp.async.cg.shared.global [%0], [%1], 16;"
                         :: "r"(dst), "l"(src));
        }
    };

    const int KT = K >> 5;
    #pragma unroll
    for (int s = 0; s < STG - 1; s++) {
        if (s < KT) load_stage(s, s * BK);
        asm volatile("cp.async.commit_group;");
    }

    for (int kt = 0; kt < KT; kt++) {
        asm volatile("cp.async.wait_group 2;");
        __syncthreads();
        {
            int nk = kt + STG - 1;
            if (nk < KT) load_stage(nk & 3, nk * BK);
            asm volatile("cp.async.commit_group;");
        }
        const float* As_ = As + (kt & 3) * ASTGF + (wrow * 32 + g) * AROW;
        const float* Bs_ = Bs + (kt & 3) * BSTGF + wcol * 32 + g;
        #pragma unroll
        for (int ks = 0; ks < 4; ks++) {
            const int kk = ks * 8 + tig;
            uint32_t a[2][4], b[4][2];
            #pragma unroll
            for (int fm = 0; fm < 2; fm++) {
                const float* p = As_ + fm * 16 * AROW + kk;
                a[fm][0] = __float_as_uint(p[0]);
                a[fm][1] = __float_as_uint(p[8 * AROW]);
                a[fm][2] = __float_as_uint(p[4]);
                a[fm][3] = __float_as_uint(p[8 * AROW + 4]);
            }
            #pragma unroll
            for (int fn = 0; fn < 4; fn++) {
                const float* p = Bs_ + kk * BROW + fn * 8;
                b[fn][0] = __float_as_uint(p[0]);
                b[fn][1] = __float_as_uint(p[4 * BROW]);
            }
            #pragma unroll
            for (int fm = 0; fm < 2; fm++)
                #pragma unroll
                for (int fn = 0; fn < 4; fn++)
                    mma_tf32(acc[fm][fn], a[fm], b[fn]);
        }
        __syncthreads();
    }

    // ----------------------------- epilogue --------------------------------
    const int rowBase = m0 + wrow * 32;
    const int colBase = n0 + wcol * 32;
    #pragma unroll
    for (int fm = 0; fm < 2; fm++) {
        #pragma unroll
        for (int fn = 0; fn < 4; fn++) {
            const int c = colBase + fn * 8 + tig * 2;
            float v0 = acc[fm][fn][0], v1 = acc[fm][fn][1];
            float v2 = acc[fm][fn][2], v3 = acc[fm][fn][3];
            if constexpr (MODE == 0 || MODE == 1 || MODE == 2 || MODE == 5) {
                const float b0 = bias[c], b1 = bias[c + 1];
                v0 += b0; v1 += b1; v2 += b0; v3 += b1;
            }
            if constexpr (MODE == 1) {
                v0 = fmaxf(v0, 0.f); v1 = fmaxf(v1, 0.f);
                v2 = fmaxf(v2, 0.f); v3 = fmaxf(v3, 0.f);
            }
            if constexpr (MODE == 1 || MODE == 2 || MODE == 5) {
                v0 = cvt_tf32(v0); v1 = cvt_tf32(v1);
                v2 = cvt_tf32(v2); v3 = cvt_tf32(v3);
            }
            if constexpr (MODE == 3) {
                v0 *= 0.125f; v1 *= 0.125f; v2 *= 0.125f; v3 *= 0.125f;
            }
            const int r0 = rowBase + fm * 16 + g;
            const int r1 = r0 + 8;
            if constexpr (MODE == 0 || MODE == 1) {
                *(float2*)(C + (size_t)r0 * 1024 + c) = make_float2(v0, v1);
                *(float2*)(C + (size_t)r1 * 1024 + c) = make_float2(v2, v3);
            } else if constexpr (MODE == 3) {
                float* Cz = C + (size_t)z * (1024u * 1024u);
                *(float2*)(Cz + (size_t)r0 * 1024 + c) = make_float2(v0, v1);
                *(float2*)(Cz + (size_t)r1 * 1024 + c) = make_float2(v2, v3);
            } else if constexpr (MODE == 2) {
                const int h0 = c & 15, d0 = c >> 4;
                const int h1 = (c + 1) & 15, d1 = (c + 1) >> 4;
                { const int b = r0 >> 10, i = r0 & 1023;
                  C[((size_t)(b * 16 + h0) * 1024 + i) * 64 + d0] = v0;
                  C[((size_t)(b * 16 + h1) * 1024 + i) * 64 + d1] = v1; }
                { const int b = r1 >> 10, i = r1 & 1023;
                  C[((size_t)(b * 16 + h0) * 1024 + i) * 64 + d0] = v2;
                  C[((size_t)(b * 16 + h1) * 1024 + i) * 64 + d1] = v3; }
            } else if constexpr (MODE == 5) {
                const int h0 = c & 15, d0 = c >> 4;
                const int h1 = (c + 1) & 15, d1 = (c + 1) >> 4;
                { const int b = r0 >> 10, i = r0 & 1023;
                  C[((size_t)(b * 16 + h0) * 64 + d0) * 1024 + i] = v0;
                  C[((size_t)(b * 16 + h1) * 64 + d1) * 1024 + i] = v1; }
                { const int b = r1 >> 10, i = r1 & 1023;
                  C[((size_t)(b * 16 + h0) * 64 + d0) * 1024 + i] = v2;
                  C[((size_t)(b * 16 + h1) * 64 + d1) * 1024 + i] = v3; }
            } else { // MODE 4
                const int b = z >> 4, h = z & 15;
                float* base0 = C + ((size_t)(b * 1024 + r0)) * 1024;
                float* base1 = C + ((size_t)(b * 1024 + r1)) * 1024;
                base0[c * 16 + h]       = v0;
                base0[(c + 1) * 16 + h] = v1;
                base1[c * 16 + h]       = v2;
                base1[(c + 1) * 16 + h] = v3;
            }
        }
    }
}

// ---------------------------------------------------------------------------
// Row softmax over j, then p += mask1 (+mask2); writes tf32-rounded P.
// ---------------------------------------------------------------------------
__global__ void softmax_mask_k(float* __restrict__ S,
                               const float* __restrict__ m1,
                               const float* __restrict__ m2)
{
    __shared__ float red[256];
    const int r   = blockIdx.x;
    const int bh  = r >> 10;
    const int i   = r & 1023;
    const int b   = bh >> 4;
    const int tid = threadIdx.x;

    float* row = S + (size_t)r * SEQ;
    const float* mr1 = m1 + ((size_t)b * SEQ + i) * SEQ;
    const float* mr2 = m2 ? m2 + ((size_t)b * SEQ + i) * SEQ : nullptr;

    float v[4];
    #pragma unroll
    for (int c = 0; c < 4; c++) v[c] = row[tid + c*256];

    float mx = fmaxf(fmaxf(v[0], v[1]), fmaxf(v[2], v[3]));
    red[tid] = mx; __syncthreads();
    for (int s = 128; s > 0; s >>= 1) {
        if (tid < s) red[tid] = fmaxf(red[tid], red[tid + s]);
        __syncthreads();
    }
    mx = red[0]; __syncthreads();

    float e[4], sum = 0.f;
    #pragma unroll
    for (int c = 0; c < 4; c++) { e[c] = expf(v[c] - mx); sum += e[c]; }
    red[tid] = sum; __syncthreads();
    for (int s = 128; s > 0; s >>= 1) {
        if (tid < s) red[tid] += red[tid + s];
        __syncthreads();
    }
    const float inv = 1.f / red[0];

    #pragma unroll
    for (int c = 0; c < 4; c++) {
        const int j = tid + c*256;
        float p = e[c] * inv + mr1[j];
        if (mr2) p += mr2[j];
        row[j] = cvt_tf32(p);
    }
}

// ---------------------------------------------------------------------------
// out = LN(X)*g + b + res; optional tf32-rounded copy for downstream GEMMs.
// ---------------------------------------------------------------------------
__global__ void ln_res_k(const float* __restrict__ X,
                         const float* __restrict__ res,
                         const float* __restrict__ gam,
                         const float* __restrict__ bet,
                         float* __restrict__ out,
                         float* __restrict__ out_t)
{
    __shared__ float red[256];
    const int r   = blockIdx.x;
    const int tid = threadIdx.x;
    const float* xr = X   + (size_t)r * EMB;
    const float* rr = res + (size_t)r * EMB;
    float* orow     = out + (size_t)r * EMB;

    float v[4];
    #pragma unroll
    for (int c = 0; c < 4; c++) v[c] = xr[tid + c*256];

    float s = v[0] + v[1] + v[2] + v[3];
    red[tid] = s; __syncthreads();
    for (int k = 128; k > 0; k >>= 1) {
        if (tid < k) red[tid] += red[tid + k];
        __syncthreads();
    }
    const float mean = red[0] * (1.f / EMB); __syncthreads();

    float sq = 0.f;
    #pragma unroll
    for (int c = 0; c < 4; c++) { float d = v[c] - mean; sq += d * d; }
    red[tid] = sq; __syncthreads();
    for (int k = 128; k > 0; k >>= 1) {
        if (tid < k) red[tid] += red[tid + k];
        __syncthreads();
    }
    const float rstd = rsqrtf(red[0] * (1.f / EMB) + 1e-5f);

    #pragma unroll
    for (int c = 0; c < 4; c++) {
        const int j = tid + c*256;
        float o = (v[c] - mean) * rstd * gam[j] + bet[j] + rr[j];
        orow[j] = o;
        if (out_t) out_t[(size_t)r * EMB + j] = cvt_tf32(o);
    }
}

// ---------------------------------------------------------------------------
extern "C" void kernel_launch(void* const* d_in, const int* in_sizes, int n_in,
                              void* d_out, int out_size)
{
    (void)in_sizes; (void)n_in; (void)out_size;

    const float* x      = (const float*)d_in[0];
    const float* ctx    = (const float*)d_in[1];
    const float* causal = (const float*)d_in[2];
    const float* ppad   = (const float*)d_in[3];
    const float* cpad   = (const float*)d_in[4];
    const float* sa_Wq  = (const float*)d_in[5];
    const float* sa_bq  = (const float*)d_in[6];
    const float* sa_Wk  = (const float*)d_in[7];
    const float* sa_bk  = (const float*)d_in[8];
    const float* sa_Wv  = (const float*)d_in[9];
    const float* sa_bv  = (const float*)d_in[10];
    const float* ca_Wq  = (const float*)d_in[11];
    const float* ca_bq  = (const float*)d_in[12];
    const float* ca_Wk  = (const float*)d_in[13];
    const float* ca_bk  = (const float*)d_in[14];
    const float* ca_Wv  = (const float*)d_in[15];
    const float* ca_bv  = (const float*)d_in[16];
    const float* ln1_g  = (const float*)d_in[17];
    const float* ln1_b  = (const float*)d_in[18];
    const float* ln2_g  = (const float*)d_in[19];
    const float* ln2_b  = (const float*)d_in[20];
    const float* ln3_g  = (const float*)d_in[21];
    const float* ln3_b  = (const float*)d_in[22];
    const float* mlp_W1 = (const float*)d_in[23];
    const float* mlp_b1 = (const float*)d_in[24];
    const float* mlp_W2 = (const float*)d_in[25];
    const float* mlp_b2 = (const float*)d_in[26];
    float* out = (float*)d_out;

    float *cvt, *Qh, *Kt, *Vh, *S, *tmp, *x1, *x2, *x1t, *x2t, *hid;
    cudaGetSymbolAddress((void**)&cvt, g_cvt);
    cudaGetSymbolAddress((void**)&Qh,  g_Qh);
    cudaGetSymbolAddress((void**)&Kt,  g_Kt);
    cudaGetSymbolAddress((void**)&Vh,  g_Vh);
    cudaGetSymbolAddress((void**)&S,   g_S);
    cudaGetSymbolAddress((void**)&tmp, g_tmp);
    cudaGetSymbolAddress((void**)&x1,  g_x1);
    cudaGetSymbolAddress((void**)&x2,  g_x2);
    cudaGetSymbolAddress((void**)&x1t, g_x1t);
    cudaGetSymbolAddress((void**)&x2t, g_x2t);
    cudaGetSymbolAddress((void**)&hid, g_hid);

    const float* WT[8] = { cvt + 0*1048576, cvt + 1*1048576, cvt + 2*1048576,
                           cvt + 3*1048576, cvt + 4*1048576, cvt + 5*1048576,
                           cvt + 6*1048576, cvt + 7*1048576 };
    const float* XT  = cvt + 8*1048576;
    const float* CTT = cvt + 10*1048576;

    constexpr int SMEM = (4*128*36 + 4*32*72) * 4;   // 110592 bytes

    auto kPlain   = tf32gemm3<0>;
    auto kRelu    = tf32gemm3<1>;
    auto kScatter = tf32gemm3<2>;
    auto kQK      = tf32gemm3<3>;
    auto kPV      = tf32gemm3<4>;
    auto kKT      = tf32gemm3<5>;
    cudaFuncSetAttribute(kPlain,   cudaFuncAttributeMaxDynamicSharedMemorySize, SMEM);
    cudaFuncSetAttribute(kRelu,    cudaFuncAttributeMaxDynamicSharedMemorySize, SMEM);
    cudaFuncSetAttribute(kScatter, cudaFuncAttributeMaxDynamicSharedMemorySize, SMEM);
    cudaFuncSetAttribute(kQK,      cudaFuncAttributeMaxDynamicSharedMemorySize, SMEM);
    cudaFuncSetAttribute(kPV,      cudaFuncAttributeMaxDynamicSharedMemorySize, SMEM);
    cudaFuncSetAttribute(kKT,      cudaFuncAttributeMaxDynamicSharedMemorySize, SMEM);

    // ---- 0. one-shot tf32 rounding pass ----
    CvtPtrs cp;
    cp.p[0] = (const float4*)sa_Wq;  cp.p[1] = (const float4*)sa_Wk;
    cp.p[2] = (const float4*)sa_Wv;  cp.p[3] = (const float4*)ca_Wq;
    cp.p[4] = (const float4*)ca_Wk;  cp.p[5] = (const float4*)ca_Wv;
    cp.p[6] = (const float4*)mlp_W1; cp.p[7] = (const float4*)mlp_W2;
    cp.p[8]  = (const float4*)x;            cp.p[9]  = (const float4*)(x + 4*262144);
    cp.p[10] = (const float4*)ctx;          cp.p[11] = (const float4*)(ctx + 4*262144);
    cvt_all_k<<<12288, 256>>>(cp, (float4*)cvt);

    const dim3 gProj(EMB/64, NROWS/128, 1);       // (16, 16)
    const dim3 gQK(SEQ/64, SEQ/128, NB*NHD);      // (16, 8, 32)
    const dim3 gPV(1, SEQ/128, NB*NHD);           // (1, 8, 32)
    const size_t hs = (size_t)SEQ * HDD;          // 65536
    const size_t ss = (size_t)SEQ * SEQ;          // 1048576

    // ---- self-attention ----
    kScatter<<<gProj, 256, SMEM>>>(XT, WT[0], sa_bq, Qh, EMB, EMB, EMB, 0, 0);
    kKT     <<<gProj, 256, SMEM>>>(XT, WT[1], sa_bk, Kt, EMB, EMB, EMB, 0, 0);
    kScatter<<<gProj, 256, SMEM>>>(XT, WT[2], sa_bv, Vh, EMB, EMB, EMB, 0, 0);
    kQK<<<gQK, 256, SMEM>>>(Qh, Kt, nullptr, S, HDD, HDD, SEQ, hs, hs);
    softmax_mask_k<<<NB*NHD*SEQ, 256>>>(S, causal, ppad);
    kPV<<<gPV, 256, SMEM>>>(S, Vh, nullptr, tmp, SEQ, SEQ, HDD, ss, hs);
    ln_res_k<<<NROWS, 256>>>(tmp, x, ln1_g, ln1_b, x1, x1t);

    // ---- cross-attention ----
    kScatter<<<gProj, 256, SMEM>>>(x1t, WT[3], ca_bq, Qh, EMB, EMB, EMB, 0, 0);
    kKT     <<<gProj, 256, SMEM>>>(CTT, WT[4], ca_bk, Kt, EMB, EMB, EMB, 0, 0);
    kScatter<<<gProj, 256, SMEM>>>(CTT, WT[5], ca_bv, Vh, EMB, EMB, EMB, 0, 0);
    kQK<<<gQK, 256, SMEM>>>(Qh, Kt, nullptr, S, HDD, HDD, SEQ, hs, hs);
    softmax_mask_k<<<NB*NHD*SEQ, 256>>>(S, cpad, nullptr);
    kPV<<<gPV, 256, SMEM>>>(S, Vh, nullptr, tmp, SEQ, SEQ, HDD, ss, hs);
    ln_res_k<<<NROWS, 256>>>(tmp, x1, ln2_g, ln2_b, x2, x2t);

    // ---- MLP ----
    kRelu <<<gProj, 256, SMEM>>>(x2t, WT[6], mlp_b1, hid, EMB, EMB, EMB, 0, 0);
    kPlain<<<gProj, 256, SMEM>>>(hid, WT[7], mlp_b2, tmp, EMB, EMB, EMB, 0, 0);
    ln_res_k<<<NROWS, 256>>>(tmp, x2, ln3_g, ln3_b, out, nullptr);
}

// round 13
// speedup vs baseline: 1.1242x; 1.1242x over previous
#include <cuda_runtime.h>
#include <math.h>
#include <stdint.h>

#define NB   2
#define SEQ  1024
#define EMB  1024
#define NHD  16
#define HDD  64
#define NROWS (NB*SEQ)      // 2048

// ---------------- scratch (device globals) ----------------------------------
__device__ float g_cvt[12*1024*1024];   // 8 W^T pi(k) (1M ea) + xt(2M) + ctxt(2M)
__device__ float g_Qh [NB*NHD*SEQ*HDD]; // [bh][i][pi(d)]
__device__ float g_Kh [NB*NHD*SEQ*HDD]; // [bh][j][pi(d)]
__device__ float g_Vt [NB*NHD*HDD*SEQ]; // [bh][o][pi(j)]
__device__ float g_S  [NB*NHD*SEQ*SEQ]; // scores (natural j) / probs (pi(j))
__device__ float g_tmp[NROWS*EMB];
__device__ float g_x1 [NROWS*EMB];
__device__ float g_x2 [NROWS*EMB];
__device__ float g_x1t[NROWS*EMB];      // pi-permuted tf32 copies
__device__ float g_x2t[NROWS*EMB];
__device__ float g_hid[NROWS*EMB];      // pi-permuted tf32

__device__ __forceinline__ float cvt_tf32(float x) {
    uint32_t u;
    asm("cvt.rna.tf32.f32 %0, %1;" : "=r"(u) : "f"(x));
    return __uint_as_float(u);
}

// k-permutation within aligned 8-groups: order [0,4,1,5,2,6,3,7]
__device__ __forceinline__ int kp(int k) {
    return (k & ~7) | ((k & 3) << 1) | ((k & 4) >> 2);
}

__device__ __forceinline__ void mma_tf32(float* d,
                                         const uint32_t* a, const uint32_t* b) {
    asm volatile(
        "mma.sync.aligned.m16n8k8.row.col.f32.tf32.tf32.f32 "
        "{%0,%1,%2,%3}, {%4,%5,%6,%7}, {%8,%9}, {%0,%1,%2,%3};"
        : "+f"(d[0]), "+f"(d[1]), "+f"(d[2]), "+f"(d[3])
        : "r"(a[0]), "r"(a[1]), "r"(a[2]), "r"(a[3]), "r"(b[0]), "r"(b[1]));
}

// ---------------------------------------------------------------------------
// Weight transpose + tf32 round + k-permute:  W[k][n] -> WT[n][pi(k)]
// ---------------------------------------------------------------------------
struct WPtrs { const float* p[8]; };

__global__ void wtrans_k(WPtrs wp, float* __restrict__ dst)
{
    __shared__ float t[32][33];
    const float* W = wp.p[blockIdx.z];
    float* D = dst + (size_t)blockIdx.z * 1048576;
    const int n0 = blockIdx.x * 32, k0 = blockIdx.y * 32;
    const int c = threadIdx.x, r0 = threadIdx.y;
    #pragma unroll
    for (int i = 0; i < 4; i++) {
        int rr = r0 + i * 8;
        t[rr][c] = W[(size_t)(k0 + rr) * 1024 + n0 + c];
    }
    __syncthreads();
    #pragma unroll
    for (int i = 0; i < 4; i++) {
        int rr = r0 + i * 8;
        D[(size_t)(n0 + rr) * 1024 + k0 + kp(c)] = cvt_tf32(t[c][rr]);
    }
}

// x, ctx -> tf32 + k-permuted embedding dim
__global__ void xcvt_k(const float4* __restrict__ x, const float4* __restrict__ ctx,
                       float* __restrict__ dst)
{
    int i = blockIdx.x * 256 + threadIdx.x;           // float4 index, 1M total
    if (i >= 1048576) return;
    float4 v = (i < 524288) ? x[i] : ctx[i - 524288];
    int base = i * 4;                                 // j within rowspace
    dst[(base & ~1023) + kp((base & 1023) + 0)] = cvt_tf32(v.x);
    dst[(base & ~1023) + kp((base & 1023) + 1)] = cvt_tf32(v.y);
    dst[(base & ~1023) + kp((base & 1023) + 2)] = cvt_tf32(v.z);
    dst[(base & ~1023) + kp((base & 1023) + 3)] = cvt_tf32(v.w);
}

// ---------------------------------------------------------------------------
// tf32 GEMM, 128x64x32 tile, 128 threads = 4 warps (2x2), warp tile 64x32,
// 3-stage cp.async pipeline.  A: [M,K] K-major, pi(k).  B: [N,K] K-major, pi(k).
// Both tf32-rounded.  Fragment loads are LDS.64 thanks to pi.
// MODE 0: C[r*1024+c] = acc + bias[c]           (fp32, natural cols)
// MODE 1: relu(acc+bias)->tf32, cols pi-permuted (hid)
// MODE 2: head scatter Qh/Kh[((b*16+h)*1024+i)*64 + pi(d)]   tf32
// MODE 3: scores C[z*1M + r*1024 + c] = acc*0.125            (natural)
// MODE 4: pv interleave C[(b*1024+r)*1024 + c*16 + h]        (natural)
// MODE 5: Vt scatter [((b*16+h)*64+o)*1024 + pi(r)]          tf32
// ---------------------------------------------------------------------------
template<int MODE>
__global__ void __launch_bounds__(128, 2)
tf32gemm4(const float* __restrict__ A, const float* __restrict__ Bg,
          const float* __restrict__ bias, float* __restrict__ C,
          int K, int lda, int ldb, size_t astride, size_t bstride)
{
    constexpr int BM = 128, BN = 64, BK = 32, ST = 3;
    constexpr int ROWP  = 40;            // 32 + 8 pad: conflict-free LDS.64
    constexpr int ASTGF = BM * ROWP;     // 5120 floats
    constexpr int BSTGF = BN * ROWP;     // 2560 floats

    extern __shared__ float sm[];
    float* As = sm;                      // [ST][BM][ROWP]
    float* Bs = sm + ST * ASTGF;         // [ST][BN][ROWP]
    const uint32_t sAb = (uint32_t)__cvta_generic_to_shared(As);
    const uint32_t sBb = (uint32_t)__cvta_generic_to_shared(Bs);

    const int tid  = threadIdx.x;
    const int lane = tid & 31;
    const int wid  = tid >> 5;
    const int g    = lane >> 2;
    const int tig  = lane & 3;
    const int wrow = wid >> 1;           // 0..1 (64 rows each)
    const int wcol = wid & 1;            // 0..1 (32 cols each)

    const int z  = blockIdx.z;
    const int m0 = blockIdx.y * BM;
    const int n0 = blockIdx.x * BN;
    const float* Ab = A  + (size_t)z * astride;
    const float* Bb = Bg + (size_t)z * bstride;

    float acc[4][4][4];
    #pragma unroll
    for (int i = 0; i < 4; i++)
        #pragma unroll
        for (int j = 0; j < 4; j++)
            #pragma unroll
            for (int q = 0; q < 4; q++) acc[i][j][q] = 0.f;

    auto load_stage = [&](int s, int k0) {
        #pragma unroll
        for (int i = 0; i < 8; i++) {            // A: 128 rows x 8 float4
            int q   = tid + i * 128;
            int row = q >> 3, c4 = (q & 7) << 2;
            const float* src = Ab + (size_t)(m0 + row) * lda + k0 + c4;
            uint32_t dst = sAb + (uint32_t)((s * ASTGF + row * ROWP + c4) * 4);
            asm volatile("cp.async.cg.shared.global [%0], [%1], 16;"
                         :: "r"(dst), "l"(src));
        }
        #pragma unroll
        for (int i = 0; i < 4; i++) {            // B: 64 rows x 8 float4
            int q   = tid + i * 128;
            int row = q >> 3, c4 = (q & 7) << 2;
            const float* src = Bb + (size_t)(n0 + row) * ldb + k0 + c4;
            uint32_t dst = sBb + (uint32_t)((s * BSTGF + row * ROWP + c4) * 4);
            asm volatile("cp.async.cg.shared.global [%0], [%1], 16;"
                         :: "r"(dst), "l"(src));
        }
    };

    const int KT = K >> 5;
    load_stage(0, 0);
    asm volatile("cp.async.commit_group;");
    if (KT > 1) load_stage(1, BK);
    asm volatile("cp.async.commit_group;");

    for (int t = 0; t < KT; t++) {
        asm volatile("cp.async.wait_group 1;");
        __syncthreads();
        {
            int nk = t + 2;
            if (nk < KT) {
                int slot = nk % 3;
                load_stage(slot, nk * BK);
            }
            asm volatile("cp.async.commit_group;");
        }
        const int cur = t % 3;
        const float* As_ = As + cur * ASTGF + (wrow * 64 + g) * ROWP;
        const float* Bs_ = Bs + cur * BSTGF + (wcol * 32 + g) * ROWP;
        #pragma unroll
        for (int ks = 0; ks < 4; ks++) {
            const int kb = ks * 8 + tig * 2;     // pi-space: (tig, tig+4) adjacent
            uint32_t a[4][4], b[4][2];
            #pragma unroll
            for (int fm = 0; fm < 4; fm++) {
                float2 lo = *(const float2*)(As_ + fm * 16 * ROWP + kb);
                float2 hi = *(const float2*)(As_ + fm * 16 * ROWP + 8 * ROWP + kb);
                a[fm][0] = __float_as_uint(lo.x);
                a[fm][1] = __float_as_uint(hi.x);
                a[fm][2] = __float_as_uint(lo.y);
                a[fm][3] = __float_as_uint(hi.y);
            }
            #pragma unroll
            for (int fn = 0; fn < 4; fn++) {
                float2 bv = *(const float2*)(Bs_ + fn * 8 * ROWP + kb);
                b[fn][0] = __float_as_uint(bv.x);
                b[fn][1] = __float_as_uint(bv.y);
            }
            #pragma unroll
            for (int fm = 0; fm < 4; fm++)
                #pragma unroll
                for (int fn = 0; fn < 4; fn++)
                    mma_tf32(acc[fm][fn], a[fm], b[fn]);
        }
        __syncthreads();
    }

    // ----------------------------- epilogue --------------------------------
    const int rowBase = m0 + wrow * 64;
    const int colBase = n0 + wcol * 32;
    #pragma unroll
    for (int fm = 0; fm < 4; fm++) {
        #pragma unroll
        for (int fn = 0; fn < 4; fn++) {
            const int c = colBase + fn * 8 + tig * 2;   // global col (even)
            float v0 = acc[fm][fn][0], v1 = acc[fm][fn][1];
            float v2 = acc[fm][fn][2], v3 = acc[fm][fn][3];
            if constexpr (MODE == 0 || MODE == 1 || MODE == 2 || MODE == 5) {
                const float b0 = bias[c], b1 = bias[c + 1];
                v0 += b0; v1 += b1; v2 += b0; v3 += b1;
            }
            if constexpr (MODE == 1) {
                v0 = fmaxf(v0, 0.f); v1 = fmaxf(v1, 0.f);
                v2 = fmaxf(v2, 0.f); v3 = fmaxf(v3, 0.f);
            }
            if constexpr (MODE == 1 || MODE == 2 || MODE == 5) {
                v0 = cvt_tf32(v0); v1 = cvt_tf32(v1);
                v2 = cvt_tf32(v2); v3 = cvt_tf32(v3);
            }
            if constexpr (MODE == 3) {
                v0 *= 0.125f; v1 *= 0.125f; v2 *= 0.125f; v3 *= 0.125f;
            }
            const int r0 = rowBase + fm * 16 + g;
            const int r1 = r0 + 8;
            if constexpr (MODE == 0) {
                *(float2*)(C + (size_t)r0 * 1024 + c) = make_float2(v0, v1);
                *(float2*)(C + (size_t)r1 * 1024 + c) = make_float2(v2, v3);
            } else if constexpr (MODE == 1) {
                const int p0 = kp(c), p1 = kp(c + 1);
                C[(size_t)r0 * 1024 + p0] = v0;  C[(size_t)r0 * 1024 + p1] = v1;
                C[(size_t)r1 * 1024 + p0] = v2;  C[(size_t)r1 * 1024 + p1] = v3;
            } else if constexpr (MODE == 3) {
                float* Cz = C + (size_t)z * (1024u * 1024u);
                *(float2*)(Cz + (size_t)r0 * 1024 + c) = make_float2(v0, v1);
                *(float2*)(Cz + (size_t)r1 * 1024 + c) = make_float2(v2, v3);
            } else if constexpr (MODE == 2) {
                const int h0 = c & 15,       d0 = kp(c >> 4);
                const int h1 = (c + 1) & 15, d1 = kp((c + 1) >> 4);
                { const int b = r0 >> 10, i = r0 & 1023;
                  C[((size_t)(b * 16 + h0) * 1024 + i) * 64 + d0] = v0;
                  C[((size_t)(b * 16 + h1) * 1024 + i) * 64 + d1] = v1; }
                { const int b = r1 >> 10, i = r1 & 1023;
                  C[((size_t)(b * 16 + h0) * 1024 + i) * 64 + d0] = v2;
                  C[((size_t)(b * 16 + h1) * 1024 + i) * 64 + d1] = v3; }
            } else if constexpr (MODE == 5) {
                const int h0 = c & 15,       o0 = c >> 4;
                const int h1 = (c + 1) & 15, o1 = (c + 1) >> 4;
                { const int b = r0 >> 10, i = kp(r0 & 1023);
                  C[((size_t)(b * 16 + h0) * 64 + o0) * 1024 + i] = v0;
                  C[((size_t)(b * 16 + h1) * 64 + o1) * 1024 + i] = v1; }
                { const int b = r1 >> 10, i = kp(r1 & 1023);
                  C[((size_t)(b * 16 + h0) * 64 + o0) * 1024 + i] = v2;
                  C[((size_t)(b * 16 + h1) * 64 + o1) * 1024 + i] = v3; }
            } else { // MODE 4
                const int b = z >> 4, h = z & 15;
                float* base0 = C + ((size_t)(b * 1024 + r0)) * 1024;
                float* base1 = C + ((size_t)(b * 1024 + r1)) * 1024;
                base0[c * 16 + h]       = v0;
                base0[(c + 1) * 16 + h] = v1;
                base1[c * 16 + h]       = v2;
                base1[(c + 1) * 16 + h] = v3;
            }
        }
    }
}

// ---------------------------------------------------------------------------
// Row softmax over j, then p += mask1 (+mask2); writes tf32 P at pi(j).
// ---------------------------------------------------------------------------
__global__ void softmax_mask_k(float* __restrict__ S,
                               const float* __restrict__ m1,
                               const float* __restrict__ m2)
{
    __shared__ float red[256];
    const int r   = blockIdx.x;
    const int bh  = r >> 10;
    const int i   = r & 1023;
    const int b   = bh >> 4;
    const int tid = threadIdx.x;

    float* row = S + (size_t)r * SEQ;
    const float* mr1 = m1 + ((size_t)b * SEQ + i) * SEQ;
    const float* mr2 = m2 ? m2 + ((size_t)b * SEQ + i) * SEQ : nullptr;

    float v[4];
    #pragma unroll
    for (int c = 0; c < 4; c++) v[c] = row[tid + c*256];

    float mx = fmaxf(fmaxf(v[0], v[1]), fmaxf(v[2], v[3]));
    red[tid] = mx; __syncthreads();
    for (int s = 128; s > 0; s >>= 1) {
        if (tid < s) red[tid] = fmaxf(red[tid], red[tid + s]);
        __syncthreads();
    }
    mx = red[0]; __syncthreads();

    float e[4], sum = 0.f;
    #pragma unroll
    for (int c = 0; c < 4; c++) { e[c] = expf(v[c] - mx); sum += e[c]; }
    red[tid] = sum; __syncthreads();
    for (int s = 128; s > 0; s >>= 1) {
        if (tid < s) red[tid] += red[tid + s];
        __syncthreads();
    }
    const float inv = 1.f / red[0];
    __syncthreads();   // all reads of row[] done before permuted writes

    #pragma unroll
    for (int c = 0; c < 4; c++) {
        const int j = tid + c*256;
        float p = e[c] * inv + mr1[j];
        if (mr2) p += mr2[j];
        row[kp(j)] = cvt_tf32(p);
    }
}

// ---------------------------------------------------------------------------
// out = LN(X)*g + b + res; out_t = tf32 copy with pi-permuted columns.
// ---------------------------------------------------------------------------
__global__ void ln_res_k(const float* __restrict__ X,
                         const float* __restrict__ res,
                         const float* __restrict__ gam,
                         const float* __restrict__ bet,
                         float* __restrict__ out,
                         float* __restrict__ out_t)
{
    __shared__ float red[256];
    const int r   = blockIdx.x;
    const int tid = threadIdx.x;
    const float* xr = X   + (size_t)r * EMB;
    const float* rr = res + (size_t)r * EMB;
    float* orow     = out + (size_t)r * EMB;

    float v[4];
    #pragma unroll
    for (int c = 0; c < 4; c++) v[c] = xr[tid + c*256];

    float s = v[0] + v[1] + v[2] + v[3];
    red[tid] = s; __syncthreads();
    for (int k = 128; k > 0; k >>= 1) {
        if (tid < k) red[tid] += red[tid + k];
        __syncthreads();
    }
    const float mean = red[0] * (1.f / EMB); __syncthreads();

    float sq = 0.f;
    #pragma unroll
    for (int c = 0; c < 4; c++) { float d = v[c] - mean; sq += d * d; }
    red[tid] = sq; __syncthreads();
    for (int k = 128; k > 0; k >>= 1) {
        if (tid < k) red[tid] += red[tid + k];
        __syncthreads();
    }
    const float rstd = rsqrtf(red[0] * (1.f / EMB) + 1e-5f);

    #pragma unroll
    for (int c = 0; c < 4; c++) {
        const int j = tid + c*256;
        float o = (v[c] - mean) * rstd * gam[j] + bet[j] + rr[j];
        orow[j] = o;
        if (out_t) out_t[(size_t)r * EMB + kp(j)] = cvt_tf32(o);
    }
}

// ---------------------------------------------------------------------------
extern "C" void kernel_launch(void* const* d_in, const int* in_sizes, int n_in,
                              void* d_out, int out_size)
{
    (void)in_sizes; (void)n_in; (void)out_size;

    const float* x      = (const float*)d_in[0];
    const float* ctx    = (const float*)d_in[1];
    const float* causal = (const float*)d_in[2];
    const float* ppad   = (const float*)d_in[3];
    const float* cpad   = (const float*)d_in[4];
    const float* sa_Wq  = (const float*)d_in[5];
    const float* sa_bq  = (const float*)d_in[6];
    const float* sa_Wk  = (const float*)d_in[7];
    const float* sa_bk  = (const float*)d_in[8];
    const float* sa_Wv  = (const float*)d_in[9];
    const float* sa_bv  = (const float*)d_in[10];
    const float* ca_Wq  = (const float*)d_in[11];
    const float* ca_bq  = (const float*)d_in[12];
    const float* ca_Wk  = (const float*)d_in[13];
    const float* ca_bk  = (const float*)d_in[14];
    const float* ca_Wv  = (const float*)d_in[15];
    const float* ca_bv  = (const float*)d_in[16];
    const float* ln1_g  = (const float*)d_in[17];
    const float* ln1_b  = (const float*)d_in[18];
    const float* ln2_g  = (const float*)d_in[19];
    const float* ln2_b  = (const float*)d_in[20];
    const float* ln3_g  = (const float*)d_in[21];
    const float* ln3_b  = (const float*)d_in[22];
    const float* mlp_W1 = (const float*)d_in[23];
    const float* mlp_b1 = (const float*)d_in[24];
    const float* mlp_W2 = (const float*)d_in[25];
    const float* mlp_b2 = (const float*)d_in[26];
    float* out = (float*)d_out;

    float *cvt, *Qh, *Kh, *Vt, *S, *tmp, *x1, *x2, *x1t, *x2t, *hid;
    cudaGetSymbolAddress((void**)&cvt, g_cvt);
    cudaGetSymbolAddress((void**)&Qh,  g_Qh);
    cudaGetSymbolAddress((void**)&Kh,  g_Kh);
    cudaGetSymbolAddress((void**)&Vt,  g_Vt);
    cudaGetSymbolAddress((void**)&S,   g_S);
    cudaGetSymbolAddress((void**)&tmp, g_tmp);
    cudaGetSymbolAddress((void**)&x1,  g_x1);
    cudaGetSymbolAddress((void**)&x2,  g_x2);
    cudaGetSymbolAddress((void**)&x1t, g_x1t);
    cudaGetSymbolAddress((void**)&x2t, g_x2t);
    cudaGetSymbolAddress((void**)&hid, g_hid);

    const float* WT[8] = { cvt + 0*1048576, cvt + 1*1048576, cvt + 2*1048576,
                           cvt + 3*1048576, cvt + 4*1048576, cvt + 5*1048576,
                           cvt + 6*1048576, cvt + 7*1048576 };
    const float* XT  = cvt + 8*1048576;
    const float* CTT = cvt + 10*1048576;

    constexpr int SMEM = 3 * (128 + 64) * 40 * 4;   // 92160 bytes

    auto kPlain   = tf32gemm4<0>;   // MLP2
    auto kRelu    = tf32gemm4<1>;   // MLP1 -> pi-permuted hid
    auto kScatter = tf32gemm4<2>;   // Q/K head scatter (pi on d)
    auto kQK      = tf32gemm4<3>;   // scores
    auto kPV      = tf32gemm4<4>;   // P@V interleave
    auto kVT      = tf32gemm4<5>;   // V transposed scatter (pi on j)
    cudaFuncSetAttribute(kPlain,   cudaFuncAttributeMaxDynamicSharedMemorySize, SMEM);
    cudaFuncSetAttribute(kRelu,    cudaFuncAttributeMaxDynamicSharedMemorySize, SMEM);
    cudaFuncSetAttribute(kScatter, cudaFuncAttributeMaxDynamicSharedMemorySize, SMEM);
    cudaFuncSetAttribute(kQK,      cudaFuncAttributeMaxDynamicSharedMemorySize, SMEM);
    cudaFuncSetAttribute(kPV,      cudaFuncAttributeMaxDynamicSharedMemorySize, SMEM);
    cudaFuncSetAttribute(kVT,      cudaFuncAttributeMaxDynamicSharedMemorySize, SMEM);

    // ---- 0. weight transpose (pi) + x/ctx cvt (pi) ----
    WPtrs wp;
    wp.p[0] = sa_Wq;  wp.p[1] = sa_Wk;  wp.p[2] = sa_Wv;
    wp.p[3] = ca_Wq;  wp.p[4] = ca_Wk;  wp.p[5] = ca_Wv;
    wp.p[6] = mlp_W1; wp.p[7] = mlp_W2;
    wtrans_k<<<dim3(32, 32, 8), dim3(32, 8)>>>(wp, cvt);
    xcvt_k<<<4096, 256>>>((const float4*)x, (const float4*)ctx, cvt + 8*1048576);

    const dim3 gProj(EMB/64, NROWS/128, 1);       // (16, 16)
    const dim3 gQK(SEQ/64, SEQ/128, NB*NHD);      // (16, 8, 32)
    const dim3 gPV(1, SEQ/128, NB*NHD);           // (1, 8, 32)
    const size_t hs = (size_t)SEQ * HDD;          // 65536
    const size_t ss = (size_t)SEQ * SEQ;          // 1048576

    // ---- self-attention ----
    kScatter<<<gProj, 128, SMEM>>>(XT, WT[0], sa_bq, Qh, EMB, EMB, EMB, 0, 0);
    kScatter<<<gProj, 128, SMEM>>>(XT, WT[1], sa_bk, Kh, EMB, EMB, EMB, 0, 0);
    kVT     <<<gProj, 128, SMEM>>>(XT, WT[2], sa_bv, Vt, EMB, EMB, EMB, 0, 0);
    kQK<<<gQK, 128, SMEM>>>(Qh, Kh, nullptr, S, HDD, HDD, HDD, hs, hs);
    softmax_mask_k<<<NB*NHD*SEQ, 256>>>(S, causal, ppad);
    kPV<<<gPV, 128, SMEM>>>(S, Vt, nullptr, tmp, SEQ, SEQ, SEQ, ss, hs);
    ln_res_k<<<NROWS, 256>>>(tmp, x, ln1_g, ln1_b, x1, x1t);

    // ---- cross-attention ----
    kScatter<<<gProj, 128, SMEM>>>(x1t, WT[3], ca_bq, Qh, EMB, EMB, EMB, 0, 0);
    kScatter<<<gProj, 128, SMEM>>>(CTT, WT[4], ca_bk, Kh, EMB, EMB, EMB, 0, 0);
    kVT     <<<gProj, 128, SMEM>>>(CTT, WT[5], ca_bv, Vt, EMB, EMB, EMB, 0, 0);
    kQK<<<gQK, 128, SMEM>>>(Qh, Kh, nullptr, S, HDD, HDD, HDD, hs, hs);
    softmax_mask_k<<<NB*NHD*SEQ, 256>>>(S, cpad, nullptr);
    kPV<<<gPV, 128, SMEM>>>(S, Vt, nullptr, tmp, SEQ, SEQ, SEQ, ss, hs);
    ln_res_k<<<NROWS, 256>>>(tmp, x1, ln2_g, ln2_b, x2, x2t);

    // ---- MLP ----
    kRelu <<<gProj, 128, SMEM>>>(x2t, WT[6], mlp_b1, hid, EMB, EMB, EMB, 0, 0);
    kPlain<<<gProj, 128, SMEM>>>(hid, WT[7], mlp_b2, tmp, EMB, EMB, EMB, 0, 0);
    ln_res_k<<<NROWS, 256>>>(tmp, x2, ln3_g, ln3_b, out, nullptr);
}

// round 14
// speedup vs baseline: 1.1269x; 1.0025x over previous
#include <cuda_runtime.h>
#include <math.h>
#include <stdint.h>

#define NB   2
#define SEQ  1024
#define EMB  1024
#define NHD  16
#define HDD  64
#define NROWS (NB*SEQ)      // 2048

// ---------------- scratch (device globals) ----------------------------------
__device__ float g_cvt[12*1024*1024];   // 8 W^T pi(k) (1M ea) + xt(2M) + ctxt(2M)
__device__ float g_Qh [NB*NHD*SEQ*HDD]; // [bh][i][pi(d)]
__device__ float g_Kh [NB*NHD*SEQ*HDD]; // [bh][j][pi(d)]
__device__ float g_Vt [NB*NHD*HDD*SEQ]; // [bh][o][pi(j)]
__device__ float g_S  [NB*NHD*SEQ*SEQ]; // scores (natural j) / probs (pi(j))
__device__ float g_tmp[NROWS*EMB];
__device__ float g_x1 [NROWS*EMB];
__device__ float g_x2 [NROWS*EMB];
__device__ float g_x1t[NROWS*EMB];      // pi-permuted tf32 copies
__device__ float g_x2t[NROWS*EMB];
__device__ float g_hid[NROWS*EMB];      // pi-permuted tf32

__device__ __forceinline__ float cvt_tf32(float x) {
    uint32_t u;
    asm("cvt.rna.tf32.f32 %0, %1;" : "=r"(u) : "f"(x));
    return __uint_as_float(u);
}

// k-permutation within aligned 8-groups: order [0,4,1,5,2,6,3,7]
__device__ __forceinline__ int kp(int k) {
    return (k & ~7) | ((k & 3) << 1) | ((k & 4) >> 2);
}

__device__ __forceinline__ void mma_tf32(float* d,
                                         const uint32_t* a, const uint32_t* b) {
    asm volatile(
        "mma.sync.aligned.m16n8k8.row.col.f32.tf32.tf32.f32 "
        "{%0,%1,%2,%3}, {%4,%5,%6,%7}, {%8,%9}, {%0,%1,%2,%3};"
        : "+f"(d[0]), "+f"(d[1]), "+f"(d[2]), "+f"(d[3])
        : "r"(a[0]), "r"(a[1]), "r"(a[2]), "r"(a[3]), "r"(b[0]), "r"(b[1]));
}

// ---------------------------------------------------------------------------
// Weight transpose + tf32 round + k-permute:  W[k][n] -> WT[n][pi(k)]
// ---------------------------------------------------------------------------
struct WPtrs { const float* p[8]; };

__global__ void wtrans_k(WPtrs wp, float* __restrict__ dst)
{
    __shared__ float t[32][33];
    const float* W = wp.p[blockIdx.z];
    float* D = dst + (size_t)blockIdx.z * 1048576;
    const int n0 = blockIdx.x * 32, k0 = blockIdx.y * 32;
    const int c = threadIdx.x, r0 = threadIdx.y;
    #pragma unroll
    for (int i = 0; i < 4; i++) {
        int rr = r0 + i * 8;
        t[rr][c] = W[(size_t)(k0 + rr) * 1024 + n0 + c];
    }
    __syncthreads();
    #pragma unroll
    for (int i = 0; i < 4; i++) {
        int rr = r0 + i * 8;
        D[(size_t)(n0 + rr) * 1024 + k0 + kp(c)] = cvt_tf32(t[c][rr]);
    }
}

// x, ctx -> tf32 + k-permuted embedding dim
__global__ void xcvt_k(const float4* __restrict__ x, const float4* __restrict__ ctx,
                       float* __restrict__ dst)
{
    int i = blockIdx.x * 256 + threadIdx.x;           // float4 index, 1M total
    if (i >= 1048576) return;
    float4 v = (i < 524288) ? x[i] : ctx[i - 524288];
    int base = i * 4;
    dst[(base & ~1023) + kp((base & 1023) + 0)] = cvt_tf32(v.x);
    dst[(base & ~1023) + kp((base & 1023) + 1)] = cvt_tf32(v.y);
    dst[(base & ~1023) + kp((base & 1023) + 2)] = cvt_tf32(v.z);
    dst[(base & ~1023) + kp((base & 1023) + 3)] = cvt_tf32(v.w);
}

// ---------------------------------------------------------------------------
// tf32 GEMM, 128x64x32 tile, 128 threads = 4 warps (2x2), warp tile 64x32,
// 3-stage cp.async pipeline + 2-deep register fragment pipeline.
// A: [M,K] K-major pi(k).  B: [N,K] K-major pi(k).  Both tf32-rounded.
// MODE 0: C[r*1024+c] = acc + bias[c]           (fp32, natural cols)
// MODE 1: relu(acc+bias)->tf32, cols pi-permuted (hid)
// MODE 2: head scatter Qh/Kh[((b*16+h)*1024+i)*64 + pi(d)]   tf32
// MODE 3: scores C[z*1M + r*1024 + c] = acc*0.125            (natural)
// MODE 4: pv interleave C[(b*1024+r)*1024 + c*16 + h]        (natural)
// MODE 5: Vt scatter [((b*16+h)*64+o)*1024 + pi(r)]          tf32
// ---------------------------------------------------------------------------
template<int MODE>
__global__ void __launch_bounds__(128, 2)
tf32gemm4(const float* __restrict__ A, const float* __restrict__ Bg,
          const float* __restrict__ bias, float* __restrict__ C,
          int K, int lda, int ldb, size_t astride, size_t bstride)
{
    constexpr int BM = 128, BN = 64, BK = 32, ST = 3;
    constexpr int ROWP  = 40;            // 32 + 8 pad: conflict-free LDS.64
    constexpr int ASTGF = BM * ROWP;     // 5120 floats
    constexpr int BSTGF = BN * ROWP;     // 2560 floats

    extern __shared__ float sm[];
    float* As = sm;                      // [ST][BM][ROWP]
    float* Bs = sm + ST * ASTGF;         // [ST][BN][ROWP]
    const uint32_t sAb = (uint32_t)__cvta_generic_to_shared(As);
    const uint32_t sBb = (uint32_t)__cvta_generic_to_shared(Bs);

    const int tid  = threadIdx.x;
    const int lane = tid & 31;
    const int wid  = tid >> 5;
    const int g    = lane >> 2;
    const int tig  = lane & 3;
    const int wrow = wid >> 1;           // 0..1 (64 rows each)
    const int wcol = wid & 1;            // 0..1 (32 cols each)

    const int z  = blockIdx.z;
    const int m0 = blockIdx.y * BM;
    const int n0 = blockIdx.x * BN;
    const float* Ab = A  + (size_t)z * astride;
    const float* Bb = Bg + (size_t)z * bstride;

    float acc[4][4][4];
    #pragma unroll
    for (int i = 0; i < 4; i++)
        #pragma unroll
        for (int j = 0; j < 4; j++)
            #pragma unroll
            for (int q = 0; q < 4; q++) acc[i][j][q] = 0.f;

    auto load_stage = [&](int s, int k0) {
        #pragma unroll
        for (int i = 0; i < 8; i++) {            // A: 128 rows x 8 float4
            int q   = tid + i * 128;
            int row = q >> 3, c4 = (q & 7) << 2;
            const float* src = Ab + (size_t)(m0 + row) * lda + k0 + c4;
            uint32_t dst = sAb + (uint32_t)((s * ASTGF + row * ROWP + c4) * 4);
            asm volatile("cp.async.cg.shared.global [%0], [%1], 16;"
                         :: "r"(dst), "l"(src));
        }
        #pragma unroll
        for (int i = 0; i < 4; i++) {            // B: 64 rows x 8 float4
            int q   = tid + i * 128;
            int row = q >> 3, c4 = (q & 7) << 2;
            const float* src = Bb + (size_t)(n0 + row) * ldb + k0 + c4;
            uint32_t dst = sBb + (uint32_t)((s * BSTGF + row * ROWP + c4) * 4);
            asm volatile("cp.async.cg.shared.global [%0], [%1], 16;"
                         :: "r"(dst), "l"(src));
        }
    };

    const int KT = K >> 5;
    load_stage(0, 0);
    asm volatile("cp.async.commit_group;");
    if (KT > 1) load_stage(1, BK);
    asm volatile("cp.async.commit_group;");

    for (int t = 0; t < KT; t++) {
        asm volatile("cp.async.wait_group 1;");
        __syncthreads();
        {
            int nk = t + 2;
            if (nk < KT) {
                int slot = nk % 3;
                load_stage(slot, nk * BK);
            }
            asm volatile("cp.async.commit_group;");
        }
        const int cur = t % 3;
        const float* As_ = As + cur * ASTGF + (wrow * 64 + g) * ROWP;
        const float* Bs_ = Bs + cur * BSTGF + (wcol * 32 + g) * ROWP;

        // 2-deep register fragment pipeline over the 4 k-steps
        uint32_t a[2][4][4], b[2][4][2];
        auto ldfrag = [&](int ks, int buf) {
            const int kb = ks * 8 + tig * 2;     // pi-space: (tig, tig+4) adjacent
            #pragma unroll
            for (int fm = 0; fm < 4; fm++) {
                float2 lo = *(const float2*)(As_ + fm * 16 * ROWP + kb);
                float2 hi = *(const float2*)(As_ + fm * 16 * ROWP + 8 * ROWP + kb);
                a[buf][fm][0] = __float_as_uint(lo.x);
                a[buf][fm][1] = __float_as_uint(hi.x);
                a[buf][fm][2] = __float_as_uint(lo.y);
                a[buf][fm][3] = __float_as_uint(hi.y);
            }
            #pragma unroll
            for (int fn = 0; fn < 4; fn++) {
                float2 bv = *(const float2*)(Bs_ + fn * 8 * ROWP + kb);
                b[buf][fn][0] = __float_as_uint(bv.x);
                b[buf][fn][1] = __float_as_uint(bv.y);
            }
        };

        ldfrag(0, 0);
        #pragma unroll
        for (int ks = 0; ks < 4; ks++) {
            if (ks < 3) ldfrag(ks + 1, (ks + 1) & 1);
            const int cb = ks & 1;
            #pragma unroll
            for (int fm = 0; fm < 4; fm++)
                #pragma unroll
                for (int fn = 0; fn < 4; fn++)
                    mma_tf32(acc[fm][fn], a[cb][fm], b[cb][fn]);
        }
        __syncthreads();
    }

    // ----------------------------- epilogue --------------------------------
    const int rowBase = m0 + wrow * 64;
    const int colBase = n0 + wcol * 32;
    #pragma unroll
    for (int fm = 0; fm < 4; fm++) {
        #pragma unroll
        for (int fn = 0; fn < 4; fn++) {
            const int c = colBase + fn * 8 + tig * 2;   // global col (even)
            float v0 = acc[fm][fn][0], v1 = acc[fm][fn][1];
            float v2 = acc[fm][fn][2], v3 = acc[fm][fn][3];
            if constexpr (MODE == 0 || MODE == 1 || MODE == 2 || MODE == 5) {
                const float b0 = bias[c], b1 = bias[c + 1];
                v0 += b0; v1 += b1; v2 += b0; v3 += b1;
            }
            if constexpr (MODE == 1) {
                v0 = fmaxf(v0, 0.f); v1 = fmaxf(v1, 0.f);
                v2 = fmaxf(v2, 0.f); v3 = fmaxf(v3, 0.f);
            }
            if constexpr (MODE == 1 || MODE == 2 || MODE == 5) {
                v0 = cvt_tf32(v0); v1 = cvt_tf32(v1);
                v2 = cvt_tf32(v2); v3 = cvt_tf32(v3);
            }
            if constexpr (MODE == 3) {
                v0 *= 0.125f; v1 *= 0.125f; v2 *= 0.125f; v3 *= 0.125f;
            }
            const int r0 = rowBase + fm * 16 + g;
            const int r1 = r0 + 8;
            if constexpr (MODE == 0) {
                *(float2*)(C + (size_t)r0 * 1024 + c) = make_float2(v0, v1);
                *(float2*)(C + (size_t)r1 * 1024 + c) = make_float2(v2, v3);
            } else if constexpr (MODE == 1) {
                const int p0 = kp(c), p1 = kp(c + 1);
                C[(size_t)r0 * 1024 + p0] = v0;  C[(size_t)r0 * 1024 + p1] = v1;
                C[(size_t)r1 * 1024 + p0] = v2;  C[(size_t)r1 * 1024 + p1] = v3;
            } else if constexpr (MODE == 3) {
                float* Cz = C + (size_t)z * (1024u * 1024u);
                *(float2*)(Cz + (size_t)r0 * 1024 + c) = make_float2(v0, v1);
                *(float2*)(Cz + (size_t)r1 * 1024 + c) = make_float2(v2, v3);
            } else if constexpr (MODE == 2) {
                const int h0 = c & 15,       d0 = kp(c >> 4);
                const int h1 = (c + 1) & 15, d1 = kp((c + 1) >> 4);
                { const int b = r0 >> 10, i = r0 & 1023;
                  C[((size_t)(b * 16 + h0) * 1024 + i) * 64 + d0] = v0;
                  C[((size_t)(b * 16 + h1) * 1024 + i) * 64 + d1] = v1; }
                { const int b = r1 >> 10, i = r1 & 1023;
                  C[((size_t)(b * 16 + h0) * 1024 + i) * 64 + d0] = v2;
                  C[((size_t)(b * 16 + h1) * 1024 + i) * 64 + d1] = v3; }
            } else if constexpr (MODE == 5) {
                const int h0 = c & 15,       o0 = c >> 4;
                const int h1 = (c + 1) & 15, o1 = (c + 1) >> 4;
                { const int b = r0 >> 10, i = kp(r0 & 1023);
                  C[((size_t)(b * 16 + h0) * 64 + o0) * 1024 + i] = v0;
                  C[((size_t)(b * 16 + h1) * 64 + o1) * 1024 + i] = v1; }
                { const int b = r1 >> 10, i = kp(r1 & 1023);
                  C[((size_t)(b * 16 + h0) * 64 + o0) * 1024 + i] = v2;
                  C[((size_t)(b * 16 + h1) * 64 + o1) * 1024 + i] = v3; }
            } else { // MODE 4
                const int b = z >> 4, h = z & 15;
                float* base0 = C + ((size_t)(b * 1024 + r0)) * 1024;
                float* base1 = C + ((size_t)(b * 1024 + r1)) * 1024;
                base0[c * 16 + h]       = v0;
                base0[(c + 1) * 16 + h] = v1;
                base1[c * 16 + h]       = v2;
                base1[(c + 1) * 16 + h] = v3;
            }
        }
    }
}

// ---------------------------------------------------------------------------
// Row softmax over j, then p += mask1 (+mask2); writes tf32 P at pi(j).
// ---------------------------------------------------------------------------
__global__ void softmax_mask_k(float* __restrict__ S,
                               const float* __restrict__ m1,
                               const float* __restrict__ m2)
{
    __shared__ float red[256];
    const int r   = blockIdx.x;
    const int bh  = r >> 10;
    const int i   = r & 1023;
    const int b   = bh >> 4;
    const int tid = threadIdx.x;

    float* row = S + (size_t)r * SEQ;
    const float* mr1 = m1 + ((size_t)b * SEQ + i) * SEQ;
    const float* mr2 = m2 ? m2 + ((size_t)b * SEQ + i) * SEQ : nullptr;

    float v[4];
    #pragma unroll
    for (int c = 0; c < 4; c++) v[c] = row[tid + c*256];

    float mx = fmaxf(fmaxf(v[0], v[1]), fmaxf(v[2], v[3]));
    red[tid] = mx; __syncthreads();
    for (int s = 128; s > 0; s >>= 1) {
        if (tid < s) red[tid] = fmaxf(red[tid], red[tid + s]);
        __syncthreads();
    }
    mx = red[0]; __syncthreads();

    float e[4], sum = 0.f;
    #pragma unroll
    for (int c = 0; c < 4; c++) { e[c] = expf(v[c] - mx); sum += e[c]; }
    red[tid] = sum; __syncthreads();
    for (int s = 128; s > 0; s >>= 1) {
        if (tid < s) red[tid] += red[tid + s];
        __syncthreads();
    }
    const float inv = 1.f / red[0];
    __syncthreads();   // all reads of row[] done before permuted writes

    #pragma unroll
    for (int c = 0; c < 4; c++) {
        const int j = tid + c*256;
        float p = e[c] * inv + mr1[j];
        if (mr2) p += mr2[j];
        row[kp(j)] = cvt_tf32(p);
    }
}

// ---------------------------------------------------------------------------
// out = LN(X)*g + b + res; out_t = tf32 copy with pi-permuted columns.
// ---------------------------------------------------------------------------
__global__ void ln_res_k(const float* __restrict__ X,
                         const float* __restrict__ res,
                         const float* __restrict__ gam,
                         const float* __restrict__ bet,
                         float* __restrict__ out,
                         float* __restrict__ out_t)
{
    __shared__ float red[256];
    const int r   = blockIdx.x;
    const int tid = threadIdx.x;
    const float* xr = X   + (size_t)r * EMB;
    const float* rr = res + (size_t)r * EMB;
    float* orow     = out + (size_t)r * EMB;

    float v[4];
    #pragma unroll
    for (int c = 0; c < 4; c++) v[c] = xr[tid + c*256];

    float s = v[0] + v[1] + v[2] + v[3];
    red[tid] = s; __syncthreads();
    for (int k = 128; k > 0; k >>= 1) {
        if (tid < k) red[tid] += red[tid + k];
        __syncthreads();
    }
    const float mean = red[0] * (1.f / EMB); __syncthreads();

    float sq = 0.f;
    #pragma unroll
    for (int c = 0; c < 4; c++) { float d = v[c] - mean; sq += d * d; }
    red[tid] = sq; __syncthreads();
    for (int k = 128; k > 0; k >>= 1) {
        if (tid < k) red[tid] += red[tid + k];
        __syncthreads();
    }
    const float rstd = rsqrtf(red[0] * (1.f / EMB) + 1e-5f);

    #pragma unroll
    for (int c = 0; c < 4; c++) {
        const int j = tid + c*256;
        float o = (v[c] - mean) * rstd * gam[j] + bet[j] + rr[j];
        orow[j] = o;
        if (out_t) out_t[(size_t)r * EMB + kp(j)] = cvt_tf32(o);
    }
}

// ---------------------------------------------------------------------------
extern "C" void kernel_launch(void* const* d_in, const int* in_sizes, int n_in,
                              void* d_out, int out_size)
{
    (void)in_sizes; (void)n_in; (void)out_size;

    const float* x      = (const float*)d_in[0];
    const float* ctx    = (const float*)d_in[1];
    const float* causal = (const float*)d_in[2];
    const float* ppad   = (const float*)d_in[3];
    const float* cpad   = (const float*)d_in[4];
    const float* sa_Wq  = (const float*)d_in[5];
    const float* sa_bq  = (const float*)d_in[6];
    const float* sa_Wk  = (const float*)d_in[7];
    const float* sa_bk  = (const float*)d_in[8];
    const float* sa_Wv  = (const float*)d_in[9];
    const float* sa_bv  = (const float*)d_in[10];
    const float* ca_Wq  = (const float*)d_in[11];
    const float* ca_bq  = (const float*)d_in[12];
    const float* ca_Wk  = (const float*)d_in[13];
    const float* ca_bk  = (const float*)d_in[14];
    const float* ca_Wv  = (const float*)d_in[15];
    const float* ca_bv  = (const float*)d_in[16];
    const float* ln1_g  = (const float*)d_in[17];
    const float* ln1_b  = (const float*)d_in[18];
    const float* ln2_g  = (const float*)d_in[19];
    const float* ln2_b  = (const float*)d_in[20];
    const float* ln3_g  = (const float*)d_in[21];
    const float* ln3_b  = (const float*)d_in[22];
    const float* mlp_W1 = (const float*)d_in[23];
    const float* mlp_b1 = (const float*)d_in[24];
    const float* mlp_W2 = (const float*)d_in[25];
    const float* mlp_b2 = (const float*)d_in[26];
    float* out = (float*)d_out;

    float *cvt, *Qh, *Kh, *Vt, *S, *tmp, *x1, *x2, *x1t, *x2t, *hid;
    cudaGetSymbolAddress((void**)&cvt, g_cvt);
    cudaGetSymbolAddress((void**)&Qh,  g_Qh);
    cudaGetSymbolAddress((void**)&Kh,  g_Kh);
    cudaGetSymbolAddress((void**)&Vt,  g_Vt);
    cudaGetSymbolAddress((void**)&S,   g_S);
    cudaGetSymbolAddress((void**)&tmp, g_tmp);
    cudaGetSymbolAddress((void**)&x1,  g_x1);
    cudaGetSymbolAddress((void**)&x2,  g_x2);
    cudaGetSymbolAddress((void**)&x1t, g_x1t);
    cudaGetSymbolAddress((void**)&x2t, g_x2t);
    cudaGetSymbolAddress((void**)&hid, g_hid);

    const float* WT[8] = { cvt + 0*1048576, cvt + 1*1048576, cvt + 2*1048576,
                           cvt + 3*1048576, cvt + 4*1048576, cvt + 5*1048576,
                           cvt + 6*1048576, cvt + 7*1048576 };
    const float* XT  = cvt + 8*1048576;
    const float* CTT = cvt + 10*1048576;

    constexpr int SMEM = 3 * (128 + 64) * 40 * 4;   // 92160 bytes

    auto kPlain   = tf32gemm4<0>;   // MLP2
    auto kRelu    = tf32gemm4<1>;   // MLP1 -> pi-permuted hid
    auto kScatter = tf32gemm4<2>;   // Q/K head scatter (pi on d)
    auto kQK      = tf32gemm4<3>;   // scores
    auto kPV      = tf32gemm4<4>;   // P@V interleave
    auto kVT      = tf32gemm4<5>;   // V transposed scatter (pi on j)
    cudaFuncSetAttribute(kPlain,   cudaFuncAttributeMaxDynamicSharedMemorySize, SMEM);
    cudaFuncSetAttribute(kRelu,    cudaFuncAttributeMaxDynamicSharedMemorySize, SMEM);
    cudaFuncSetAttribute(kScatter, cudaFuncAttributeMaxDynamicSharedMemorySize, SMEM);
    cudaFuncSetAttribute(kQK,      cudaFuncAttributeMaxDynamicSharedMemorySize, SMEM);
    cudaFuncSetAttribute(kPV,      cudaFuncAttributeMaxDynamicSharedMemorySize, SMEM);
    cudaFuncSetAttribute(kVT,      cudaFuncAttributeMaxDynamicSharedMemorySize, SMEM);

    // ---- 0. weight transpose (pi) + x/ctx cvt (pi) ----
    WPtrs wp;
    wp.p[0] = sa_Wq;  wp.p[1] = sa_Wk;  wp.p[2] = sa_Wv;
    wp.p[3] = ca_Wq;  wp.p[4] = ca_Wk;  wp.p[5] = ca_Wv;
    wp.p[6] = mlp_W1; wp.p[7] = mlp_W2;
    wtrans_k<<<dim3(32, 32, 8), dim3(32, 8)>>>(wp, cvt);
    xcvt_k<<<4096, 256>>>((const float4*)x, (const float4*)ctx, cvt + 8*1048576);

    const dim3 gProj(EMB/64, NROWS/128, 1);       // (16, 16)
    const dim3 gQK(SEQ/64, SEQ/128, NB*NHD);      // (16, 8, 32)
    const dim3 gPV(1, SEQ/128, NB*NHD);           // (1, 8, 32)
    const size_t hs = (size_t)SEQ * HDD;          // 65536
    const size_t ss = (size_t)SEQ * SEQ;          // 1048576

    // ---- self-attention ----
    kScatter<<<gProj, 128, SMEM>>>(XT, WT[0], sa_bq, Qh, EMB, EMB, EMB, 0, 0);
    kScatter<<<gProj, 128, SMEM>>>(XT, WT[1], sa_bk, Kh, EMB, EMB, EMB, 0, 0);
    kVT     <<<gProj, 128, SMEM>>>(XT, WT[2], sa_bv, Vt, EMB, EMB, EMB, 0, 0);
    kQK<<<gQK, 128, SMEM>>>(Qh, Kh, nullptr, S, HDD, HDD, HDD, hs, hs);
    softmax_mask_k<<<NB*NHD*SEQ, 256>>>(S, causal, ppad);
    kPV<<<gPV, 128, SMEM>>>(S, Vt, nullptr, tmp, SEQ, SEQ, SEQ, ss, hs);
    ln_res_k<<<NROWS, 256>>>(tmp, x, ln1_g, ln1_b, x1, x1t);

    // ---- cross-attention ----
    kScatter<<<gProj, 128, SMEM>>>(x1t, WT[3], ca_bq, Qh, EMB, EMB, EMB, 0, 0);
    kScatter<<<gProj, 128, SMEM>>>(CTT, WT[4], ca_bk, Kh, EMB, EMB, EMB, 0, 0);
    kVT     <<<gProj, 128, SMEM>>>(CTT, WT[5], ca_bv, Vt, EMB, EMB, EMB, 0, 0);
    kQK<<<gQK, 128, SMEM>>>(Qh, Kh, nullptr, S, HDD, HDD, HDD, hs, hs);
    softmax_mask_k<<<NB*NHD*SEQ, 256>>>(S, cpad, nullptr);
    kPV<<<gPV, 128, SMEM>>>(S, Vt, nullptr, tmp, SEQ, SEQ, SEQ, ss, hs);
    ln_res_k<<<NROWS, 256>>>(tmp, x1, ln2_g, ln2_b, x2, x2t);

    // ---- MLP ----
    kRelu <<<gProj, 128, SMEM>>>(x2t, WT[6], mlp_b1, hid, EMB, EMB, EMB, 0, 0);
    kPlain<<<gProj, 128, SMEM>>>(hid, WT[7], mlp_b2, tmp, EMB, EMB, EMB, 0, 0);
    ln_res_k<<<NROWS, 256>>>(tmp, x2, ln3_g, ln3_b, out, nullptr);
}

// round 16
// speedup vs baseline: 1.2127x; 1.0761x over previous
#include <cuda_runtime.h>
#include <math.h>
#include <stdint.h>

#define NB   2
#define SEQ  1024
#define EMB  1024
#define NHD  16
#define HDD  64
#define NROWS (NB*SEQ)      // 2048

// ---------------- scratch (device globals) ----------------------------------
__device__ float g_cvt[12*1024*1024];   // 8 W^T pi(k) (1M ea) + xt(2M) + ctxt(2M)
__device__ float g_Qh [NB*NHD*SEQ*HDD]; // [bh][i][pi(d)]
__device__ float g_Kh [NB*NHD*SEQ*HDD]; // self K
__device__ float g_Vt [NB*NHD*HDD*SEQ]; // self V transposed
__device__ float g_Kh2[NB*NHD*SEQ*HDD]; // cross K
__device__ float g_Vt2[NB*NHD*HDD*SEQ]; // cross V transposed
__device__ float g_S  [NB*NHD*SEQ*SEQ]; // scores (natural j) / probs (pi(j))
__device__ float g_tmp[NROWS*EMB];
__device__ float g_x1 [NROWS*EMB];
__device__ float g_x2 [NROWS*EMB];
__device__ float g_x1t[NROWS*EMB];
__device__ float g_x2t[NROWS*EMB];
__device__ float g_hid[NROWS*EMB];

__device__ __forceinline__ float cvt_tf32(float x) {
    uint32_t u;
    asm("cvt.rna.tf32.f32 %0, %1;" : "=r"(u) : "f"(x));
    return __uint_as_float(u);
}

// k-permutation within aligned 8-groups: order [0,4,1,5,2,6,3,7]
__device__ __forceinline__ int kp(int k) {
    return (k & ~7) | ((k & 3) << 1) | ((k & 4) >> 2);
}

__device__ __forceinline__ void mma_tf32(float* d,
                                         const uint32_t* a, const uint32_t* b) {
    asm volatile(
        "mma.sync.aligned.m16n8k8.row.col.f32.tf32.tf32.f32 "
        "{%0,%1,%2,%3}, {%4,%5,%6,%7}, {%8,%9}, {%0,%1,%2,%3};"
        : "+f"(d[0]), "+f"(d[1]), "+f"(d[2]), "+f"(d[3])
        : "r"(a[0]), "r"(a[1]), "r"(a[2]), "r"(a[3]), "r"(b[0]), "r"(b[1]));
}

// ---------------------------------------------------------------------------
// Weight transpose + tf32 round + k-permute:  W[k][n] -> WT[n][pi(k)]
// ---------------------------------------------------------------------------
struct WPtrs { const float* p[8]; };

__global__ void wtrans_k(WPtrs wp, float* __restrict__ dst)
{
    __shared__ float t[32][33];
    const float* W = wp.p[blockIdx.z];
    float* D = dst + (size_t)blockIdx.z * 1048576;
    const int n0 = blockIdx.x * 32, k0 = blockIdx.y * 32;
    const int c = threadIdx.x, r0 = threadIdx.y;
    #pragma unroll
    for (int i = 0; i < 4; i++) {
        int rr = r0 + i * 8;
        t[rr][c] = W[(size_t)(k0 + rr) * 1024 + n0 + c];
    }
    __syncthreads();
    #pragma unroll
    for (int i = 0; i < 4; i++) {
        int rr = r0 + i * 8;
        D[(size_t)(n0 + rr) * 1024 + k0 + kp(c)] = cvt_tf32(t[c][rr]);
    }
}

// x, ctx -> tf32 + k-permuted embedding dim
__global__ void xcvt_k(const float4* __restrict__ x, const float4* __restrict__ ctx,
                       float* __restrict__ dst)
{
    int i = blockIdx.x * 256 + threadIdx.x;
    if (i >= 1048576) return;
    float4 v = (i < 524288) ? x[i] : ctx[i - 524288];
    int base = i * 4;
    dst[(base & ~1023) + kp((base & 1023) + 0)] = cvt_tf32(v.x);
    dst[(base & ~1023) + kp((base & 1023) + 1)] = cvt_tf32(v.y);
    dst[(base & ~1023) + kp((base & 1023) + 2)] = cvt_tf32(v.z);
    dst[(base & ~1023) + kp((base & 1023) + 3)] = cvt_tf32(v.w);
}

// ---------------------------------------------------------------------------
// tf32 GEMM. BM=128, BN=FN*16, 128 threads = 4 warps (2x2), warp tile 64x(FN*8).
// ST-stage cp.async pipeline. A: [M,K] K-major pi(k). B: [N,K] K-major pi(k).
// emode 0: C[r*1024+c] = acc + bias[c]           (fp32)
// emode 1: relu(acc+bias)->tf32, cols pi-permuted
// emode 2: head scatter [((b*16+h)*1024+i)*64 + pi(d)]  tf32
// emode 3: scores C[z*1M + r*1024 + c] = acc*0.125
// emode 4: pv interleave C[(b*1024+r)*1024 + c*16 + h]
// emode 5: Vt scatter [((b*16+h)*64+o)*1024 + pi(r)]    tf32
// MODE 6:  multi-projection; per-z {A,W,bias,dst,emode} from ProjArgs.
// ---------------------------------------------------------------------------
struct ProjArgs {
    const float* A[5];
    const float* W[5];
    const float* bias[5];
    float*       dst[5];
    int          mode[5];
};

template<int FN, int ST, int MODE>
__global__ void __launch_bounds__(128, 2)
tf32gemm5(ProjArgs pa,
          const float* __restrict__ Ain, const float* __restrict__ Bin,
          const float* __restrict__ biasin, float* __restrict__ Cin,
          int Kin, int lda, int ldb, size_t astride, size_t bstride)
{
    constexpr int BM = 128, BN = FN * 16, BK = 32;
    constexpr int ROWP  = 40;
    constexpr int ASTGF = BM * ROWP;
    constexpr int BSTGF = BN * ROWP;

    extern __shared__ float sm[];
    float* As = sm;                      // [ST][BM][ROWP]
    float* Bs = sm + ST * ASTGF;         // [ST][BN][ROWP]
    const uint32_t sAb = (uint32_t)__cvta_generic_to_shared(As);
    const uint32_t sBb = (uint32_t)__cvta_generic_to_shared(Bs);

    const int tid  = threadIdx.x;
    const int lane = tid & 31;
    const int wid  = tid >> 5;
    const int g    = lane >> 2;
    const int tig  = lane & 3;
    const int wrow = wid >> 1;           // 0..1 (64 M-rows each)
    const int wcol = wid & 1;            // 0..1 (FN*8 N-cols each)

    const int z  = blockIdx.z;
    const int m0 = blockIdx.y * BM;
    const int n0 = blockIdx.x * BN;

    const float* A; const float* Bg; const float* bias; float* C;
    int K, LDA, LDB, emode;
    if constexpr (MODE == 6) {
        A = pa.A[z]; Bg = pa.W[z]; bias = pa.bias[z]; C = pa.dst[z];
        K = 1024; LDA = 1024; LDB = 1024; emode = pa.mode[z];
    } else {
        A = Ain + (size_t)z * astride; Bg = Bin + (size_t)z * bstride;
        bias = biasin; C = Cin;
        K = Kin; LDA = lda; LDB = ldb; emode = MODE;
    }

    float acc[4][FN][4];
    #pragma unroll
    for (int i = 0; i < 4; i++)
        #pragma unroll
        for (int j = 0; j < FN; j++)
            #pragma unroll
            for (int q = 0; q < 4; q++) acc[i][j][q] = 0.f;

    auto load_stage = [&](int s, int k0) {
        #pragma unroll
        for (int i = 0; i < 8; i++) {            // A: 128 rows x 8 float4
            int q   = tid + i * 128;
            int row = q >> 3, c4 = (q & 7) << 2;
            const float* src = A + (size_t)(m0 + row) * LDA + k0 + c4;
            uint32_t dst = sAb + (uint32_t)((s * ASTGF + row * ROWP + c4) * 4);
            asm volatile("cp.async.cg.shared.global [%0], [%1], 16;"
                         :: "r"(dst), "l"(src));
        }
        #pragma unroll
        for (int i = 0; i < FN; i++) {           // B: BN rows x 8 float4
            int q   = tid + i * 128;
            int row = q >> 3, c4 = (q & 7) << 2;
            const float* src = Bg + (size_t)(n0 + row) * LDB + k0 + c4;
            uint32_t dst = sBb + (uint32_t)((s * BSTGF + row * ROWP + c4) * 4);
            asm volatile("cp.async.cg.shared.global [%0], [%1], 16;"
                         :: "r"(dst), "l"(src));
        }
    };

    auto compute = [&](int slot) {
        const float* As_ = As + slot * ASTGF + (wrow * 64 + g) * ROWP;
        const float* Bs_ = Bs + slot * BSTGF + (wcol * (FN * 8) + g) * ROWP;
        #pragma unroll
        for (int ks = 0; ks < 4; ks++) {
            const int kb = ks * 8 + tig * 2;
            uint32_t a[4][4], b[FN][2];
            #pragma unroll
            for (int fm = 0; fm < 4; fm++) {
                float2 lo = *(const float2*)(As_ + fm * 16 * ROWP + kb);
                float2 hi = *(const float2*)(As_ + fm * 16 * ROWP + 8 * ROWP + kb);
                a[fm][0] = __float_as_uint(lo.x);
                a[fm][1] = __float_as_uint(hi.x);
                a[fm][2] = __float_as_uint(lo.y);
                a[fm][3] = __float_as_uint(hi.y);
            }
            #pragma unroll
            for (int fn = 0; fn < FN; fn++) {
                float2 bv = *(const float2*)(Bs_ + fn * 8 * ROWP + kb);
                b[fn][0] = __float_as_uint(bv.x);
                b[fn][1] = __float_as_uint(bv.y);
            }
            #pragma unroll
            for (int fm = 0; fm < 4; fm++)
                #pragma unroll
                for (int fn = 0; fn < FN; fn++)
                    mma_tf32(acc[fm][fn], a[fm], b[fn]);
        }
    };

    const int KT = K >> 5;
    if constexpr (ST == 3) {
        load_stage(0, 0);
        asm volatile("cp.async.commit_group;");
        if (KT > 1) load_stage(1, BK);
        asm volatile("cp.async.commit_group;");
        for (int t = 0; t < KT; t++) {
            asm volatile("cp.async.wait_group 1;");
            __syncthreads();
            int nk = t + 2;
            if (nk < KT) load_stage(nk % 3, nk * BK);
            asm volatile("cp.async.commit_group;");
            compute(t % 3);
            __syncthreads();
        }
    } else {   // ST == 2 double buffer
        load_stage(0, 0);
        asm volatile("cp.async.commit_group;");
        if (KT > 1) load_stage(1, BK);
        asm volatile("cp.async.commit_group;");
        for (int t = 0; t < KT; t++) {
            asm volatile("cp.async.wait_group 1;");
            __syncthreads();
            compute(t & 1);
            __syncthreads();
            int nk = t + 2;
            if (nk < KT) load_stage(nk & 1, nk * BK);
            asm volatile("cp.async.commit_group;");
        }
    }

    // ----------------------------- epilogue --------------------------------
    const int rowBase = m0 + wrow * 64;
    const int colBase = n0 + wcol * (FN * 8);
    #pragma unroll
    for (int fm = 0; fm < 4; fm++) {
        #pragma unroll
        for (int fn = 0; fn < FN; fn++) {
            const int c = colBase + fn * 8 + tig * 2;
            float v0 = acc[fm][fn][0], v1 = acc[fm][fn][1];
            float v2 = acc[fm][fn][2], v3 = acc[fm][fn][3];
            if (emode == 0 || emode == 1 || emode == 2 || emode == 5) {
                const float b0 = bias[c], b1 = bias[c + 1];
                v0 += b0; v1 += b1; v2 += b0; v3 += b1;
            }
            if (emode == 1) {
                v0 = fmaxf(v0, 0.f); v1 = fmaxf(v1, 0.f);
                v2 = fmaxf(v2, 0.f); v3 = fmaxf(v3, 0.f);
            }
            if (emode == 1 || emode == 2 || emode == 5) {
                v0 = cvt_tf32(v0); v1 = cvt_tf32(v1);
                v2 = cvt_tf32(v2); v3 = cvt_tf32(v3);
            }
            if (emode == 3) {
                v0 *= 0.125f; v1 *= 0.125f; v2 *= 0.125f; v3 *= 0.125f;
            }
            const int r0 = rowBase + fm * 16 + g;
            const int r1 = r0 + 8;
            if (emode == 0) {
                *(float2*)(C + (size_t)r0 * 1024 + c) = make_float2(v0, v1);
                *(float2*)(C + (size_t)r1 * 1024 + c) = make_float2(v2, v3);
            } else if (emode == 1) {
                const int p0 = kp(c), p1 = kp(c + 1);
                C[(size_t)r0 * 1024 + p0] = v0;  C[(size_t)r0 * 1024 + p1] = v1;
                C[(size_t)r1 * 1024 + p0] = v2;  C[(size_t)r1 * 1024 + p1] = v3;
            } else if (emode == 3) {
                float* Cz = C + (size_t)z * (1024u * 1024u);
                *(float2*)(Cz + (size_t)r0 * 1024 + c) = make_float2(v0, v1);
                *(float2*)(Cz + (size_t)r1 * 1024 + c) = make_float2(v2, v3);
            } else if (emode == 2) {
                const int h0 = c & 15,       d0 = kp(c >> 4);
                const int h1 = (c + 1) & 15, d1 = kp((c + 1) >> 4);
                { const int b = r0 >> 10, i = r0 & 1023;
                  C[((size_t)(b * 16 + h0) * 1024 + i) * 64 + d0] = v0;
                  C[((size_t)(b * 16 + h1) * 1024 + i) * 64 + d1] = v1; }
                { const int b = r1 >> 10, i = r1 & 1023;
                  C[((size_t)(b * 16 + h0) * 1024 + i) * 64 + d0] = v2;
                  C[((size_t)(b * 16 + h1) * 1024 + i) * 64 + d1] = v3; }
            } else if (emode == 5) {
                const int h0 = c & 15,       o0 = c >> 4;
                const int h1 = (c + 1) & 15, o1 = (c + 1) >> 4;
                { const int b = r0 >> 10, i = kp(r0 & 1023);
                  C[((size_t)(b * 16 + h0) * 64 + o0) * 1024 + i] = v0;
                  C[((size_t)(b * 16 + h1) * 64 + o1) * 1024 + i] = v1; }
                { const int b = r1 >> 10, i = kp(r1 & 1023);
                  C[((size_t)(b * 16 + h0) * 64 + o0) * 1024 + i] = v2;
                  C[((size_t)(b * 16 + h1) * 64 + o1) * 1024 + i] = v3; }
            } else { // emode 4
                const int b = z >> 4, h = z & 15;
                float* base0 = C + ((size_t)(b * 1024 + r0)) * 1024;
                float* base1 = C + ((size_t)(b * 1024 + r1)) * 1024;
                base0[c * 16 + h]       = v0;
                base0[(c + 1) * 16 + h] = v1;
                base1[c * 16 + h]       = v2;
                base1[(c + 1) * 16 + h] = v3;
            }
        }
    }
}

// ---------------------------------------------------------------------------
// Row softmax over j, then p += mask1 (+mask2); writes tf32 P at pi(j).
// ---------------------------------------------------------------------------
__global__ void softmax_mask_k(float* __restrict__ S,
                               const float* __restrict__ m1,
                               const float* __restrict__ m2)
{
    __shared__ float red[256];
    const int r   = blockIdx.x;
    const int bh  = r >> 10;
    const int i   = r & 1023;
    const int b   = bh >> 4;
    const int tid = threadIdx.x;

    float* row = S + (size_t)r * SEQ;
    const float* mr1 = m1 + ((size_t)b * SEQ + i) * SEQ;
    const float* mr2 = m2 ? m2 + ((size_t)b * SEQ + i) * SEQ : nullptr;

    float v[4];
    #pragma unroll
    for (int c = 0; c < 4; c++) v[c] = row[tid + c*256];

    float mx = fmaxf(fmaxf(v[0], v[1]), fmaxf(v[2], v[3]));
    red[tid] = mx; __syncthreads();
    for (int s = 128; s > 0; s >>= 1) {
        if (tid < s) red[tid] = fmaxf(red[tid], red[tid + s]);
        __syncthreads();
    }
    mx = red[0]; __syncthreads();

    float e[4], sum = 0.f;
    #pragma unroll
    for (int c = 0; c < 4; c++) { e[c] = expf(v[c] - mx); sum += e[c]; }
    red[tid] = sum; __syncthreads();
    for (int s = 128; s > 0; s >>= 1) {
        if (tid < s) red[tid] += red[tid + s];
        __syncthreads();
    }
    const float inv = 1.f / red[0];
    __syncthreads();   // all reads of row[] done before permuted writes

    #pragma unroll
    for (int c = 0; c < 4; c++) {
        const int j = tid + c*256;
        float p = e[c] * inv + mr1[j];
        if (mr2) p += mr2[j];
        row[kp(j)] = cvt_tf32(p);
    }
}

// ---------------------------------------------------------------------------
// out = LN(X)*g + b + res; out_t = tf32 copy with pi-permuted columns.
// ---------------------------------------------------------------------------
__global__ void ln_res_k(const float* __restrict__ X,
                         const float* __restrict__ res,
                         const float* __restrict__ gam,
                         const float* __restrict__ bet,
                         float* __restrict__ out,
                         float* __restrict__ out_t)
{
    __shared__ float red[256];
    const int r   = blockIdx.x;
    const int tid = threadIdx.x;
    const float* xr = X   + (size_t)r * EMB;
    const float* rr = res + (size_t)r * EMB;
    float* orow     = out + (size_t)r * EMB;

    float v[4];
    #pragma unroll
    for (int c = 0; c < 4; c++) v[c] = xr[tid + c*256];

    float s = v[0] + v[1] + v[2] + v[3];
    red[tid] = s; __syncthreads();
    for (int k = 128; k > 0; k >>= 1) {
        if (tid < k) red[tid] += red[tid + k];
        __syncthreads();
    }
    const float mean = red[0] * (1.f / EMB); __syncthreads();

    float sq = 0.f;
    #pragma unroll
    for (int c = 0; c < 4; c++) { float d = v[c] - mean; sq += d * d; }
    red[tid] = sq; __syncthreads();
    for (int k = 128; k > 0; k >>= 1) {
        if (tid < k) red[tid] += red[tid + k];
        __syncthreads();
    }
    const float rstd = rsqrtf(red[0] * (1.f / EMB) + 1e-5f);

    #pragma unroll
    for (int c = 0; c < 4; c++) {
        const int j = tid + c*256;
        float o = (v[c] - mean) * rstd * gam[j] + bet[j] + rr[j];
        orow[j] = o;
        if (out_t) out_t[(size_t)r * EMB + kp(j)] = cvt_tf32(o);
    }
}

// ---------------------------------------------------------------------------
extern "C" void kernel_launch(void* const* d_in, const int* in_sizes, int n_in,
                              void* d_out, int out_size)
{
    (void)in_sizes; (void)n_in; (void)out_size;

    const float* x      = (const float*)d_in[0];
    const float* ctx    = (const float*)d_in[1];
    const float* causal = (const float*)d_in[2];
    const float* ppad   = (const float*)d_in[3];
    const float* cpad   = (const float*)d_in[4];
    const float* sa_Wq  = (const float*)d_in[5];
    const float* sa_bq  = (const float*)d_in[6];
    const float* sa_Wk  = (const float*)d_in[7];
    const float* sa_bk  = (const float*)d_in[8];
    const float* sa_Wv  = (const float*)d_in[9];
    const float* sa_bv  = (const float*)d_in[10];
    const float* ca_Wq  = (const float*)d_in[11];
    const float* ca_bq  = (const float*)d_in[12];
    const float* ca_Wk  = (const float*)d_in[13];
    const float* ca_bk  = (const float*)d_in[14];
    const float* ca_Wv  = (const float*)d_in[15];
    const float* ca_bv  = (const float*)d_in[16];
    const float* ln1_g  = (const float*)d_in[17];
    const float* ln1_b  = (const float*)d_in[18];
    const float* ln2_g  = (const float*)d_in[19];
    const float* ln2_b  = (const float*)d_in[20];
    const float* ln3_g  = (const float*)d_in[21];
    const float* ln3_b  = (const float*)d_in[22];
    const float* mlp_W1 = (const float*)d_in[23];
    const float* mlp_b1 = (const float*)d_in[24];
    const float* mlp_W2 = (const float*)d_in[25];
    const float* mlp_b2 = (const float*)d_in[26];
    float* out = (float*)d_out;

    float *cvt, *Qh, *Kh, *Vt, *Kh2, *Vt2, *S, *tmp, *x1, *x2, *x1t, *x2t, *hid;
    cudaGetSymbolAddress((void**)&cvt, g_cvt);
    cudaGetSymbolAddress((void**)&Qh,  g_Qh);
    cudaGetSymbolAddress((void**)&Kh,  g_Kh);
    cudaGetSymbolAddress((void**)&Vt,  g_Vt);
    cudaGetSymbolAddress((void**)&Kh2, g_Kh2);
    cudaGetSymbolAddress((void**)&Vt2, g_Vt2);
    cudaGetSymbolAddress((void**)&S,   g_S);
    cudaGetSymbolAddress((void**)&tmp, g_tmp);
    cudaGetSymbolAddress((void**)&x1,  g_x1);
    cudaGetSymbolAddress((void**)&x2,  g_x2);
    cudaGetSymbolAddress((void**)&x1t, g_x1t);
    cudaGetSymbolAddress((void**)&x2t, g_x2t);
    cudaGetSymbolAddress((void**)&hid, g_hid);

    const float* WT[8] = { cvt + 0*1048576, cvt + 1*1048576, cvt + 2*1048576,
                           cvt + 3*1048576, cvt + 4*1048576, cvt + 5*1048576,
                           cvt + 6*1048576, cvt + 7*1048576 };
    const float* XT  = cvt + 8*1048576;
    const float* CTT = cvt + 10*1048576;

    constexpr int SM82 = 2 * (128 + 128) * 40 * 4;   // 81920 (FN=8, ST=2)
    constexpr int SM92 = 3 * (128 +  64) * 40 * 4;   // 92160 (FN=4, ST=3)

    auto kQKV   = tf32gemm5<8, 2, 6>;   // merged projections (wide-N)
    auto kProj1 = tf32gemm5<4, 3, 6>;   // single projection (cross Q)
    auto kQK    = tf32gemm5<8, 2, 3>;   // scores
    auto kPV    = tf32gemm5<4, 3, 4>;   // P@V interleave
    auto kRelu  = tf32gemm5<4, 3, 1>;   // MLP1
    auto kPlain = tf32gemm5<4, 3, 0>;   // MLP2
    cudaFuncSetAttribute(kQKV,   cudaFuncAttributeMaxDynamicSharedMemorySize, SM82);
    cudaFuncSetAttribute(kProj1, cudaFuncAttributeMaxDynamicSharedMemorySize, SM92);
    cudaFuncSetAttribute(kQK,    cudaFuncAttributeMaxDynamicSharedMemorySize, SM82);
    cudaFuncSetAttribute(kPV,    cudaFuncAttributeMaxDynamicSharedMemorySize, SM92);
    cudaFuncSetAttribute(kRelu,  cudaFuncAttributeMaxDynamicSharedMemorySize, SM92);
    cudaFuncSetAttribute(kPlain, cudaFuncAttributeMaxDynamicSharedMemorySize, SM92);

    // ---- 0. weight transpose (pi) + x/ctx cvt (pi) ----
    WPtrs wp;
    wp.p[0] = sa_Wq;  wp.p[1] = sa_Wk;  wp.p[2] = sa_Wv;
    wp.p[3] = ca_Wq;  wp.p[4] = ca_Wk;  wp.p[5] = ca_Wv;
    wp.p[6] = mlp_W1; wp.p[7] = mlp_W2;
    wtrans_k<<<dim3(32, 32, 8), dim3(32, 8)>>>(wp, cvt);
    xcvt_k<<<4096, 256>>>((const float4*)x, (const float4*)ctx, cvt + 8*1048576);

    const size_t hs = (size_t)SEQ * HDD;          // 65536
    const size_t ss = (size_t)SEQ * SEQ;          // 1048576
    ProjArgs pz = {};                              // dummy for non-MODE6

    // ---- merged projections: self Q,K,V + cross K,V (all ready now) ----
    ProjArgs pa = {};
    pa.A[0] = XT;  pa.W[0] = WT[0]; pa.bias[0] = sa_bq; pa.dst[0] = Qh;  pa.mode[0] = 2;
    pa.A[1] = XT;  pa.W[1] = WT[1]; pa.bias[1] = sa_bk; pa.dst[1] = Kh;  pa.mode[1] = 2;
    pa.A[2] = XT;  pa.W[2] = WT[2]; pa.bias[2] = sa_bv; pa.dst[2] = Vt;  pa.mode[2] = 5;
    pa.A[3] = CTT; pa.W[3] = WT[4]; pa.bias[3] = ca_bk; pa.dst[3] = Kh2; pa.mode[3] = 2;
    pa.A[4] = CTT; pa.W[4] = WT[5]; pa.bias[4] = ca_bv; pa.dst[4] = Vt2; pa.mode[4] = 5;
    kQKV<<<dim3(8, 16, 5), 128, SM82>>>(pa, nullptr, nullptr, nullptr, nullptr,
                                        0, 0, 0, 0, 0);

    // ---- self-attention ----
    kQK<<<dim3(8, 8, 32), 128, SM82>>>(pz, Qh, Kh, nullptr, S, HDD, HDD, HDD, hs, hs);
    softmax_mask_k<<<NB*NHD*SEQ, 256>>>(S, causal, ppad);
    kPV<<<dim3(1, 8, 32), 128, SM92>>>(pz, S, Vt, nullptr, tmp, SEQ, SEQ, SEQ, ss, hs);
    ln_res_k<<<NROWS, 256>>>(tmp, x, ln1_g, ln1_b, x1, x1t);

    // ---- cross-attention (K/V already projected) ----
    ProjArgs pq = {};
    pq.A[0] = x1t; pq.W[0] = WT[3]; pq.bias[0] = ca_bq; pq.dst[0] = Qh; pq.mode[0] = 2;
    kProj1<<<dim3(16, 16, 1), 128, SM92>>>(pq, nullptr, nullptr, nullptr, nullptr,
                                           0, 0, 0, 0, 0);
    kQK<<<dim3(8, 8, 32), 128, SM82>>>(pz, Qh, Kh2, nullptr, S, HDD, HDD, HDD, hs, hs);
    softmax_mask_k<<<NB*NHD*SEQ, 256>>>(S, cpad, nullptr);
    kPV<<<dim3(1, 8, 32), 128, SM92>>>(pz, S, Vt2, nullptr, tmp, SEQ, SEQ, SEQ, ss, hs);
    ln_res_k<<<NROWS, 256>>>(tmp, x1, ln2_g, ln2_b, x2, x2t);

    // ---- MLP ----
    kRelu <<<dim3(16, 16, 1), 128, SM92>>>(pz, x2t, WT[6], mlp_b1, hid,
                                           EMB, EMB, EMB, 0, 0);
    kPlain<<<dim3(16, 16, 1), 128, SM92>>>(pz, hid, WT[7], mlp_b2, tmp,
                                           EMB, EMB, EMB, 0, 0);
    ln_res_k<<<NROWS, 256>>>(tmp, x2, ln3_g, ln3_b, out, nullptr);
}

// round 17
// speedup vs baseline: 1.2164x; 1.0031x over previous
#include <cuda_runtime.h>
#include <math.h>
#include <stdint.h>

#define NB   2
#define SEQ  1024
#define EMB  1024
#define NHD  16
#define HDD  64
#define NROWS (NB*SEQ)      // 2048

// ---------------- scratch (device globals) ----------------------------------
__device__ float g_cvt[12*1024*1024];   // 8 W^T pi(k) (1M ea) + xt(2M) + ctxt(2M)
__device__ float g_Qh [NB*NHD*SEQ*HDD]; // [bh][i][pi(d)]
__device__ float g_Kh [NB*NHD*SEQ*HDD]; // self K
__device__ float g_Vt [NB*NHD*HDD*SEQ]; // self V transposed [bh][o][pi(j)]
__device__ float g_Kh2[NB*NHD*SEQ*HDD]; // cross K
__device__ float g_Vt2[NB*NHD*HDD*SEQ]; // cross V transposed
__device__ float g_S  [NB*NHD*SEQ*SEQ]; // raw scaled scores (natural j)
__device__ float g_part[32*1024*8*2];   // per (row, jtile) partial (max, expsum)
__device__ float g_stat[32*1024*2];     // per row (max, 1/sum)
__device__ float g_msum[NB*SEQ*SEQ];    // combined self mask
__device__ float g_tmp[NROWS*EMB];
__device__ float g_x1 [NROWS*EMB];
__device__ float g_x2 [NROWS*EMB];
__device__ float g_x1t[NROWS*EMB];
__device__ float g_x2t[NROWS*EMB];
__device__ float g_hid[NROWS*EMB];

__device__ __forceinline__ float cvt_tf32(float x) {
    uint32_t u;
    asm("cvt.rna.tf32.f32 %0, %1;" : "=r"(u) : "f"(x));
    return __uint_as_float(u);
}

// k-permutation within aligned 8-groups: order [0,4,1,5,2,6,3,7]
__device__ __forceinline__ int kp(int k) {
    return (k & ~7) | ((k & 3) << 1) | ((k & 4) >> 2);
}

__device__ __forceinline__ void mma_tf32(float* d,
                                         const uint32_t* a, const uint32_t* b) {
    asm volatile(
        "mma.sync.aligned.m16n8k8.row.col.f32.tf32.tf32.f32 "
        "{%0,%1,%2,%3}, {%4,%5,%6,%7}, {%8,%9}, {%0,%1,%2,%3};"
        : "+f"(d[0]), "+f"(d[1]), "+f"(d[2]), "+f"(d[3])
        : "r"(a[0]), "r"(a[1]), "r"(a[2]), "r"(a[3]), "r"(b[0]), "r"(b[1]));
}

// ---------------------------------------------------------------------------
struct WPtrs { const float* p[8]; };

__global__ void wtrans_k(WPtrs wp, float* __restrict__ dst)
{
    __shared__ float t[32][33];
    const float* W = wp.p[blockIdx.z];
    float* D = dst + (size_t)blockIdx.z * 1048576;
    const int n0 = blockIdx.x * 32, k0 = blockIdx.y * 32;
    const int c = threadIdx.x, r0 = threadIdx.y;
    #pragma unroll
    for (int i = 0; i < 4; i++) {
        int rr = r0 + i * 8;
        t[rr][c] = W[(size_t)(k0 + rr) * 1024 + n0 + c];
    }
    __syncthreads();
    #pragma unroll
    for (int i = 0; i < 4; i++) {
        int rr = r0 + i * 8;
        D[(size_t)(n0 + rr) * 1024 + k0 + kp(c)] = cvt_tf32(t[c][rr]);
    }
}

__global__ void xcvt_k(const float4* __restrict__ x, const float4* __restrict__ ctx,
                       float* __restrict__ dst)
{
    int i = blockIdx.x * 256 + threadIdx.x;
    if (i >= 1048576) return;
    float4 v = (i < 524288) ? x[i] : ctx[i - 524288];
    int base = i * 4;
    dst[(base & ~1023) + kp((base & 1023) + 0)] = cvt_tf32(v.x);
    dst[(base & ~1023) + kp((base & 1023) + 1)] = cvt_tf32(v.y);
    dst[(base & ~1023) + kp((base & 1023) + 2)] = cvt_tf32(v.z);
    dst[(base & ~1023) + kp((base & 1023) + 3)] = cvt_tf32(v.w);
}

__global__ void maskadd_k(const float4* __restrict__ a, const float4* __restrict__ b,
                          float4* __restrict__ o)
{
    int i = blockIdx.x * 256 + threadIdx.x;     // 524288 float4s
    float4 x = a[i], y = b[i];
    o[i] = make_float4(x.x + y.x, x.y + y.y, x.z + y.z, x.w + y.w);
}

// combine 8 jtile partials per row -> (max, 1/sum)
__global__ void stat_combine_k(const float2* __restrict__ part, float2* __restrict__ stat)
{
    int r = blockIdx.x * 256 + threadIdx.x;     // 32768 rows
    float2 p[8];
    float M = -1e30f;
    #pragma unroll
    for (int j = 0; j < 8; j++) { p[j] = part[(size_t)r * 8 + j]; M = fmaxf(M, p[j].x); }
    float S = 0.f;
    #pragma unroll
    for (int j = 0; j < 8; j++) S += p[j].y * expf(p[j].x - M);
    stat[r] = make_float2(M, 1.f / S);
}

// ---------------------------------------------------------------------------
// tf32 GEMM. BM=128, BN=FN*16, 128 threads = 4 warps (2x2), warp tile 64x(FN*8).
// MODE 3 additionally emits per (row, jtile) softmax partials via `biasin`
// (cast to float2* partial buffer).  MODE 6: multi-projection via ProjArgs.
// ---------------------------------------------------------------------------
struct ProjArgs {
    const float* A[5];
    const float* W[5];
    const float* bias[5];
    float*       dst[5];
    int          mode[5];
};

template<int FN, int ST, int MODE>
__global__ void __launch_bounds__(128, 2)
tf32gemm5(ProjArgs pa,
          const float* __restrict__ Ain, const float* __restrict__ Bin,
          const float* __restrict__ biasin, float* __restrict__ Cin,
          int Kin, int lda, int ldb, size_t astride, size_t bstride)
{
    constexpr int BM = 128, BN = FN * 16, BK = 32;
    constexpr int ROWP  = 40;
    constexpr int ASTGF = BM * ROWP;
    constexpr int BSTGF = BN * ROWP;

    extern __shared__ float sm[];
    float* As = sm;
    float* Bs = sm + ST * ASTGF;
    const uint32_t sAb = (uint32_t)__cvta_generic_to_shared(As);
    const uint32_t sBb = (uint32_t)__cvta_generic_to_shared(Bs);

    const int tid  = threadIdx.x;
    const int lane = tid & 31;
    const int wid  = tid >> 5;
    const int g    = lane >> 2;
    const int tig  = lane & 3;
    const int wrow = wid >> 1;
    const int wcol = wid & 1;

    const int z  = blockIdx.z;
    const int m0 = blockIdx.y * BM;
    const int n0 = blockIdx.x * BN;

    const float* A; const float* Bg; const float* bias; float* C;
    int K, LDA, LDB, emode;
    if constexpr (MODE == 6) {
        A = pa.A[z]; Bg = pa.W[z]; bias = pa.bias[z]; C = pa.dst[z];
        K = 1024; LDA = 1024; LDB = 1024; emode = pa.mode[z];
    } else {
        A = Ain + (size_t)z * astride; Bg = Bin + (size_t)z * bstride;
        bias = biasin; C = Cin;
        K = Kin; LDA = lda; LDB = ldb; emode = MODE;
    }

    float acc[4][FN][4];
    #pragma unroll
    for (int i = 0; i < 4; i++)
        #pragma unroll
        for (int j = 0; j < FN; j++)
            #pragma unroll
            for (int q = 0; q < 4; q++) acc[i][j][q] = 0.f;

    auto load_stage = [&](int s, int k0) {
        #pragma unroll
        for (int i = 0; i < 8; i++) {
            int q   = tid + i * 128;
            int row = q >> 3, c4 = (q & 7) << 2;
            const float* src = A + (size_t)(m0 + row) * LDA + k0 + c4;
            uint32_t dst = sAb + (uint32_t)((s * ASTGF + row * ROWP + c4) * 4);
            asm volatile("cp.async.cg.shared.global [%0], [%1], 16;"
                         :: "r"(dst), "l"(src));
        }
        #pragma unroll
        for (int i = 0; i < FN; i++) {
            int q   = tid + i * 128;
            int row = q >> 3, c4 = (q & 7) << 2;
            const float* src = Bg + (size_t)(n0 + row) * LDB + k0 + c4;
            uint32_t dst = sBb + (uint32_t)((s * BSTGF + row * ROWP + c4) * 4);
            asm volatile("cp.async.cg.shared.global [%0], [%1], 16;"
                         :: "r"(dst), "l"(src));
        }
    };

    auto compute = [&](int slot) {
        const float* As_ = As + slot * ASTGF + (wrow * 64 + g) * ROWP;
        const float* Bs_ = Bs + slot * BSTGF + (wcol * (FN * 8) + g) * ROWP;
        #pragma unroll
        for (int ks = 0; ks < 4; ks++) {
            const int kb = ks * 8 + tig * 2;
            uint32_t a[4][4], b[FN][2];
            #pragma unroll
            for (int fm = 0; fm < 4; fm++) {
                float2 lo = *(const float2*)(As_ + fm * 16 * ROWP + kb);
                float2 hi = *(const float2*)(As_ + fm * 16 * ROWP + 8 * ROWP + kb);
                a[fm][0] = __float_as_uint(lo.x);
                a[fm][1] = __float_as_uint(hi.x);
                a[fm][2] = __float_as_uint(lo.y);
                a[fm][3] = __float_as_uint(hi.y);
            }
            #pragma unroll
            for (int fn = 0; fn < FN; fn++) {
                float2 bv = *(const float2*)(Bs_ + fn * 8 * ROWP + kb);
                b[fn][0] = __float_as_uint(bv.x);
                b[fn][1] = __float_as_uint(bv.y);
            }
            #pragma unroll
            for (int fm = 0; fm < 4; fm++)
                #pragma unroll
                for (int fn = 0; fn < FN; fn++)
                    mma_tf32(acc[fm][fn], a[fm], b[fn]);
        }
    };

    const int KT = K >> 5;
    if constexpr (ST == 3) {
        load_stage(0, 0);
        asm volatile("cp.async.commit_group;");
        if (KT > 1) load_stage(1, BK);
        asm volatile("cp.async.commit_group;");
        for (int t = 0; t < KT; t++) {
            asm volatile("cp.async.wait_group 1;");
            __syncthreads();
            int nk = t + 2;
            if (nk < KT) load_stage(nk % 3, nk * BK);
            asm volatile("cp.async.commit_group;");
            compute(t % 3);
            __syncthreads();
        }
    } else {
        load_stage(0, 0);
        asm volatile("cp.async.commit_group;");
        if (KT > 1) load_stage(1, BK);
        asm volatile("cp.async.commit_group;");
        for (int t = 0; t < KT; t++) {
            asm volatile("cp.async.wait_group 1;");
            __syncthreads();
            compute(t & 1);
            __syncthreads();
            int nk = t + 2;
            if (nk < KT) load_stage(nk & 1, nk * BK);
            asm volatile("cp.async.commit_group;");
        }
    }

    const int rowBase = m0 + wrow * 64;
    const int colBase = n0 + wcol * (FN * 8);

    if constexpr (MODE == 3) {
        // scores + softmax partial stats
        float* Cz = C + (size_t)z * (1024u * 1024u);
        float rm[8], rs[8];
        #pragma unroll
        for (int fm = 0; fm < 4; fm++) {
            #pragma unroll
            for (int hh = 0; hh < 2; hh++) {
                float mloc = -1e30f;
                #pragma unroll
                for (int fn = 0; fn < FN; fn++) {
                    float va = acc[fm][fn][2*hh]   * 0.125f;
                    float vb = acc[fm][fn][2*hh+1] * 0.125f;
                    mloc = fmaxf(mloc, fmaxf(va, vb));
                }
                float ssum = 0.f;
                const int r = rowBase + fm * 16 + g + hh * 8;
                #pragma unroll
                for (int fn = 0; fn < FN; fn++) {
                    float va = acc[fm][fn][2*hh]   * 0.125f;
                    float vb = acc[fm][fn][2*hh+1] * 0.125f;
                    ssum += expf(va - mloc) + expf(vb - mloc);
                    const int c = colBase + fn * 8 + tig * 2;
                    *(float2*)(Cz + (size_t)r * 1024 + c) = make_float2(va, vb);
                }
                rm[fm*2+hh] = mloc; rs[fm*2+hh] = ssum;
            }
        }
        #pragma unroll
        for (int slot = 0; slot < 8; slot++) {
            float mv = rm[slot], sv = rs[slot];
            #pragma unroll
            for (int off = 1; off < 4; off <<= 1) {
                float mo = __shfl_xor_sync(0xffffffffu, mv, off);
                float so = __shfl_xor_sync(0xffffffffu, sv, off);
                float M = fmaxf(mv, mo);
                sv = sv * expf(mv - M) + so * expf(mo - M);
                mv = M;
            }
            rm[slot] = mv; rs[slot] = sv;
        }
        __syncthreads();
        float* red = sm;                       // [2][128][2]
        if (tig == 0) {
            #pragma unroll
            for (int fm = 0; fm < 4; fm++)
                #pragma unroll
                for (int hh = 0; hh < 2; hh++) {
                    int lrow = wrow * 64 + fm * 16 + g + hh * 8;
                    red[(wcol * 128 + lrow) * 2 + 0] = rm[fm*2+hh];
                    red[(wcol * 128 + lrow) * 2 + 1] = rs[fm*2+hh];
                }
        }
        __syncthreads();
        if (tid < 128) {
            float ma = red[tid*2],       sa = red[tid*2+1];
            float mb = red[(128+tid)*2], sb = red[(128+tid)*2+1];
            float M = fmaxf(ma, mb);
            float S = sa * expf(ma - M) + sb * expf(mb - M);
            float2* part = (float2*)biasin;    // partial buffer smuggled via bias arg
            part[((size_t)z * 1024 + m0 + tid) * 8 + blockIdx.x] = make_float2(M, S);
        }
    } else {
        #pragma unroll
        for (int fm = 0; fm < 4; fm++) {
            #pragma unroll
            for (int fn = 0; fn < FN; fn++) {
                const int c = colBase + fn * 8 + tig * 2;
                float v0 = acc[fm][fn][0], v1 = acc[fm][fn][1];
                float v2 = acc[fm][fn][2], v3 = acc[fm][fn][3];
                if (emode == 0 || emode == 1 || emode == 2 || emode == 5) {
                    const float b0 = bias[c], b1 = bias[c + 1];
                    v0 += b0; v1 += b1; v2 += b0; v3 += b1;
                }
                if (emode == 1) {
                    v0 = fmaxf(v0, 0.f); v1 = fmaxf(v1, 0.f);
                    v2 = fmaxf(v2, 0.f); v3 = fmaxf(v3, 0.f);
                }
                if (emode == 1 || emode == 2 || emode == 5) {
                    v0 = cvt_tf32(v0); v1 = cvt_tf32(v1);
                    v2 = cvt_tf32(v2); v3 = cvt_tf32(v3);
                }
                const int r0 = rowBase + fm * 16 + g;
                const int r1 = r0 + 8;
                if (emode == 0) {
                    *(float2*)(C + (size_t)r0 * 1024 + c) = make_float2(v0, v1);
                    *(float2*)(C + (size_t)r1 * 1024 + c) = make_float2(v2, v3);
                } else if (emode == 1) {
                    const int p0 = kp(c), p1 = kp(c + 1);
                    C[(size_t)r0 * 1024 + p0] = v0;  C[(size_t)r0 * 1024 + p1] = v1;
                    C[(size_t)r1 * 1024 + p0] = v2;  C[(size_t)r1 * 1024 + p1] = v3;
                } else if (emode == 2) {
                    const int h0 = c & 15,       d0 = kp(c >> 4);
                    const int h1 = (c + 1) & 15, d1 = kp((c + 1) >> 4);
                    { const int b = r0 >> 10, i = r0 & 1023;
                      C[((size_t)(b * 16 + h0) * 1024 + i) * 64 + d0] = v0;
                      C[((size_t)(b * 16 + h1) * 1024 + i) * 64 + d1] = v1; }
                    { const int b = r1 >> 10, i = r1 & 1023;
                      C[((size_t)(b * 16 + h0) * 1024 + i) * 64 + d0] = v2;
                      C[((size_t)(b * 16 + h1) * 1024 + i) * 64 + d1] = v3; }
                } else if (emode == 5) {
                    const int h0 = c & 15,       o0 = c >> 4;
                    const int h1 = (c + 1) & 15, o1 = (c + 1) >> 4;
                    { const int b = r0 >> 10, i = kp(r0 & 1023);
                      C[((size_t)(b * 16 + h0) * 64 + o0) * 1024 + i] = v0;
                      C[((size_t)(b * 16 + h1) * 64 + o1) * 1024 + i] = v1; }
                    { const int b = r1 >> 10, i = kp(r1 & 1023);
                      C[((size_t)(b * 16 + h0) * 64 + o0) * 1024 + i] = v2;
                      C[((size_t)(b * 16 + h1) * 64 + o1) * 1024 + i] = v3; }
                }
            }
        }
    }
}

// ---------------------------------------------------------------------------
// Fused softmax + P@V.  Reads raw S, applies p = cvt_tf32(exp(s-M)*inv + mask)
// during the A-tile build (pi-permuted), multiplies by Vt, scatters interleaved.
// grid (1, 8, 32), 128 threads.
// ---------------------------------------------------------------------------
__global__ void __launch_bounds__(128, 2)
pv_fused_k(const float* __restrict__ S, const float* __restrict__ Vt,
           const float* __restrict__ mask, const float2* __restrict__ stat,
           float* __restrict__ dst)
{
    constexpr int ROWP = 40, RRAW = 36;
    extern __shared__ float sm[];
    float* raw0 = sm;                       // [2][128*RRAW]
    float* As   = sm + 2 * 128 * RRAW;      // [128*ROWP]
    float* Vs   = As + 128 * ROWP;          // [2][64*ROWP]
    float* mxs  = Vs + 2 * 64 * ROWP;       // [128]
    float* invs = mxs + 128;                // [128]

    const int tid  = threadIdx.x;
    const int lane = tid & 31, wid = tid >> 5;
    const int g = lane >> 2, tig = lane & 3;
    const int wrow = wid >> 1, wcol = wid & 1;
    const int z  = blockIdx.z;
    const int i0 = blockIdx.y * 128;
    const int b = z >> 4, h = z & 15;

    const float* Sz = S  + (size_t)z * 1048576 + (size_t)i0 * 1024;
    const float* Vz = Vt + (size_t)z * 65536;
    const float* Mz = mask + ((size_t)b * 1024 + i0) * 1024;

    {
        float2 st = stat[(size_t)z * 1024 + i0 + tid];
        mxs[tid] = st.x; invs[tid] = st.y;
    }

    const uint32_t rawb = (uint32_t)__cvta_generic_to_shared(raw0);
    const uint32_t vsb  = (uint32_t)__cvta_generic_to_shared(Vs);

    auto fetch = [&](int t) {
        int sl = t & 1;
        #pragma unroll
        for (int i = 0; i < 8; i++) {              // raw S: 128 x 32
            int q = tid + i * 128; int row = q >> 3, c4 = (q & 7) << 2;
            const float* src = Sz + (size_t)row * 1024 + t * 32 + c4;
            uint32_t d = rawb + (uint32_t)((sl * 128 * RRAW + row * RRAW + c4) * 4);
            asm volatile("cp.async.cg.shared.global [%0], [%1], 16;" :: "r"(d), "l"(src));
        }
        #pragma unroll
        for (int i = 0; i < 4; i++) {              // V: 64 x 32 (pi k)
            int q = tid + i * 128; int row = q >> 3, c4 = (q & 7) << 2;
            const float* src = Vz + (size_t)row * 1024 + t * 32 + c4;
            uint32_t d = vsb + (uint32_t)((sl * 64 * ROWP + row * ROWP + c4) * 4);
            asm volatile("cp.async.cg.shared.global [%0], [%1], 16;" :: "r"(d), "l"(src));
        }
    };
    fetch(0);
    asm volatile("cp.async.commit_group;");
    fetch(1);
    asm volatile("cp.async.commit_group;");

    float acc[4][4][4];
    #pragma unroll
    for (int i = 0; i < 4; i++)
        #pragma unroll
        for (int j = 0; j < 4; j++)
            #pragma unroll
            for (int q = 0; q < 4; q++) acc[i][j][q] = 0.f;

    for (int t = 0; t < 32; t++) {
        asm volatile("cp.async.wait_group 1;");
        __syncthreads();
        // transform raw[t&1] -> As (pi-permuted P)
        const float* rp = raw0 + (t & 1) * 128 * RRAW;
        #pragma unroll
        for (int it = 0; it < 8; it++) {
            int q = tid + it * 128;          // 1024 tasks: (row, g8, half)
            int row = q >> 3, sub = q & 7;
            int g8 = sub & 3, half = sub >> 2;
            const float* rb = rp + row * RRAW + g8 * 8 + half * 2;
            float2 lo = *(const float2*)(rb);        // j(2h+0), j(2h+1)
            float2 hi = *(const float2*)(rb + 4);    // j(2h+4), j(2h+5)
            float M = mxs[row], inv = invs[row];
            const float* mr = Mz + (size_t)row * 1024 + t * 32 + g8 * 8 + half * 2;
            float2 mlo = *(const float2*)(mr);
            float2 mhi = *(const float2*)(mr + 4);
            float4 o;
            o.x = cvt_tf32(expf(lo.x - M) * inv + mlo.x);
            o.y = cvt_tf32(expf(hi.x - M) * inv + mhi.x);
            o.z = cvt_tf32(expf(lo.y - M) * inv + mlo.y);
            o.w = cvt_tf32(expf(hi.y - M) * inv + mhi.y);
            *(float4*)(As + row * ROWP + g8 * 8 + half * 4) = o;
        }
        __syncthreads();
        // MMA
        const float* As_ = As + (wrow * 64 + g) * ROWP;
        const float* Bs_ = Vs + (t & 1) * 64 * ROWP + (wcol * 32 + g) * ROWP;
        #pragma unroll
        for (int ks = 0; ks < 4; ks++) {
            const int kb = ks * 8 + tig * 2;
            uint32_t a[4][4], bb[4][2];
            #pragma unroll
            for (int fm = 0; fm < 4; fm++) {
                float2 lo = *(const float2*)(As_ + fm * 16 * ROWP + kb);
                float2 hi = *(const float2*)(As_ + fm * 16 * ROWP + 8 * ROWP + kb);
                a[fm][0] = __float_as_uint(lo.x);
                a[fm][1] = __float_as_uint(hi.x);
                a[fm][2] = __float_as_uint(lo.y);
                a[fm][3] = __float_as_uint(hi.y);
            }
            #pragma unroll
            for (int fn = 0; fn < 4; fn++) {
                float2 bv = *(const float2*)(Bs_ + fn * 8 * ROWP + kb);
                bb[fn][0] = __float_as_uint(bv.x);
                bb[fn][1] = __float_as_uint(bv.y);
            }
            #pragma unroll
            for (int fm = 0; fm < 4; fm++)
                #pragma unroll
                for (int fn = 0; fn < 4; fn++)
                    mma_tf32(acc[fm][fn], a[fm], bb[fn]);
        }
        if (t + 2 < 32) fetch(t + 2);
        asm volatile("cp.async.commit_group;");
    }

    // epilogue: interleave scatter
    const int rowBase = i0 + wrow * 64;
    const int colBase = wcol * 32;
    #pragma unroll
    for (int fm = 0; fm < 4; fm++) {
        #pragma unroll
        for (int fn = 0; fn < 4; fn++) {
            const int c = colBase + fn * 8 + tig * 2;
            const int r0 = rowBase + fm * 16 + g;
            const int r1 = r0 + 8;
            float* base0 = dst + ((size_t)(b * 1024 + r0)) * 1024;
            float* base1 = dst + ((size_t)(b * 1024 + r1)) * 1024;
            base0[c * 16 + h]       = acc[fm][fn][0];
            base0[(c + 1) * 16 + h] = acc[fm][fn][1];
            base1[c * 16 + h]       = acc[fm][fn][2];
            base1[(c + 1) * 16 + h] = acc[fm][fn][3];
        }
    }
}

// ---------------------------------------------------------------------------
__global__ void ln_res_k(const float* __restrict__ X,
                         const float* __restrict__ res,
                         const float* __restrict__ gam,
                         const float* __restrict__ bet,
                         float* __restrict__ out,
                         float* __restrict__ out_t)
{
    __shared__ float red[256];
    const int r   = blockIdx.x;
    const int tid = threadIdx.x;
    const float* xr = X   + (size_t)r * EMB;
    const float* rr = res + (size_t)r * EMB;
    float* orow     = out + (size_t)r * EMB;

    float v[4];
    #pragma unroll
    for (int c = 0; c < 4; c++) v[c] = xr[tid + c*256];

    float s = v[0] + v[1] + v[2] + v[3];
    red[tid] = s; __syncthreads();
    for (int k = 128; k > 0; k >>= 1) {
        if (tid < k) red[tid] += red[tid + k];
        __syncthreads();
    }
    const float mean = red[0] * (1.f / EMB); __syncthreads();

    float sq = 0.f;
    #pragma unroll
    for (int c = 0; c < 4; c++) { float d = v[c] - mean; sq += d * d; }
    red[tid] = sq; __syncthreads();
    for (int k = 128; k > 0; k >>= 1) {
        if (tid < k) red[tid] += red[tid + k];
        __syncthreads();
    }
    const float rstd = rsqrtf(red[0] * (1.f / EMB) + 1e-5f);

    #pragma unroll
    for (int c = 0; c < 4; c++) {
        const int j = tid + c*256;
        float o = (v[c] - mean) * rstd * gam[j] + bet[j] + rr[j];
        orow[j] = o;
        if (out_t) out_t[(size_t)r * EMB + kp(j)] = cvt_tf32(o);
    }
}

// ---------------------------------------------------------------------------
extern "C" void kernel_launch(void* const* d_in, const int* in_sizes, int n_in,
                              void* d_out, int out_size)
{
    (void)in_sizes; (void)n_in; (void)out_size;

    const float* x      = (const float*)d_in[0];
    const float* ctx    = (const float*)d_in[1];
    const float* causal = (const float*)d_in[2];
    const float* ppad   = (const float*)d_in[3];
    const float* cpad   = (const float*)d_in[4];
    const float* sa_Wq  = (const float*)d_in[5];
    const float* sa_bq  = (const float*)d_in[6];
    const float* sa_Wk  = (const float*)d_in[7];
    const float* sa_bk  = (const float*)d_in[8];
    const float* sa_Wv  = (const float*)d_in[9];
    const float* sa_bv  = (const float*)d_in[10];
    const float* ca_Wq  = (const float*)d_in[11];
    const float* ca_bq  = (const float*)d_in[12];
    const float* ca_Wk  = (const float*)d_in[13];
    const float* ca_bk  = (const float*)d_in[14];
    const float* ca_Wv  = (const float*)d_in[15];
    const float* ca_bv  = (const float*)d_in[16];
    const float* ln1_g  = (const float*)d_in[17];
    const float* ln1_b  = (const float*)d_in[18];
    const float* ln2_g  = (const float*)d_in[19];
    const float* ln2_b  = (const float*)d_in[20];
    const float* ln3_g  = (const float*)d_in[21];
    const float* ln3_b  = (const float*)d_in[22];
    const float* mlp_W1 = (const float*)d_in[23];
    const float* mlp_b1 = (const float*)d_in[24];
    const float* mlp_W2 = (const float*)d_in[25];
    const float* mlp_b2 = (const float*)d_in[26];
    float* out = (float*)d_out;

    float *cvt, *Qh, *Kh, *Vt, *Kh2, *Vt2, *S, *part, *stat, *msum;
    float *tmp, *x1, *x2, *x1t, *x2t, *hid;
    cudaGetSymbolAddress((void**)&cvt,  g_cvt);
    cudaGetSymbolAddress((void**)&Qh,   g_Qh);
    cudaGetSymbolAddress((void**)&Kh,   g_Kh);
    cudaGetSymbolAddress((void**)&Vt,   g_Vt);
    cudaGetSymbolAddress((void**)&Kh2,  g_Kh2);
    cudaGetSymbolAddress((void**)&Vt2,  g_Vt2);
    cudaGetSymbolAddress((void**)&S,    g_S);
    cudaGetSymbolAddress((void**)&part, g_part);
    cudaGetSymbolAddress((void**)&stat, g_stat);
    cudaGetSymbolAddress((void**)&msum, g_msum);
    cudaGetSymbolAddress((void**)&tmp,  g_tmp);
    cudaGetSymbolAddress((void**)&x1,   g_x1);
    cudaGetSymbolAddress((void**)&x2,   g_x2);
    cudaGetSymbolAddress((void**)&x1t,  g_x1t);
    cudaGetSymbolAddress((void**)&x2t,  g_x2t);
    cudaGetSymbolAddress((void**)&hid,  g_hid);

    const float* WT[8] = { cvt + 0*1048576, cvt + 1*1048576, cvt + 2*1048576,
                           cvt + 3*1048576, cvt + 4*1048576, cvt + 5*1048576,
                           cvt + 6*1048576, cvt + 7*1048576 };
    const float* XT  = cvt + 8*1048576;
    const float* CTT = cvt + 10*1048576;

    constexpr int SM82 = 2 * (128 + 128) * 40 * 4;                    // 81920
    constexpr int SMPV = (2*128*36 + 128*40 + 2*64*40 + 256) * 4;     // 78848

    auto kQKV   = tf32gemm5<8, 2, 6>;   // merged / single projections
    auto kQK    = tf32gemm5<8, 2, 3>;   // scores + stats
    auto kRelu  = tf32gemm5<8, 2, 1>;   // MLP1
    auto kPlain = tf32gemm5<8, 2, 0>;   // MLP2
    cudaFuncSetAttribute(kQKV,   cudaFuncAttributeMaxDynamicSharedMemorySize, SM82);
    cudaFuncSetAttribute(kQK,    cudaFuncAttributeMaxDynamicSharedMemorySize, SM82);
    cudaFuncSetAttribute(kRelu,  cudaFuncAttributeMaxDynamicSharedMemorySize, SM82);
    cudaFuncSetAttribute(kPlain, cudaFuncAttributeMaxDynamicSharedMemorySize, SM82);
    cudaFuncSetAttribute(pv_fused_k, cudaFuncAttributeMaxDynamicSharedMemorySize, SMPV);

    // ---- 0. prep: weights (pi), x/ctx (pi), combined self mask ----
    WPtrs wp;
    wp.p[0] = sa_Wq;  wp.p[1] = sa_Wk;  wp.p[2] = sa_Wv;
    wp.p[3] = ca_Wq;  wp.p[4] = ca_Wk;  wp.p[5] = ca_Wv;
    wp.p[6] = mlp_W1; wp.p[7] = mlp_W2;
    wtrans_k<<<dim3(32, 32, 8), dim3(32, 8)>>>(wp, cvt);
    xcvt_k<<<4096, 256>>>((const float4*)x, (const float4*)ctx, cvt + 8*1048576);
    maskadd_k<<<2048, 256>>>((const float4*)causal, (const float4*)ppad, (float4*)msum);

    const size_t hs = (size_t)SEQ * HDD;
    ProjArgs pz = {};

    // ---- merged projections: self Q,K,V + cross K,V ----
    ProjArgs pa = {};
    pa.A[0] = XT;  pa.W[0] = WT[0]; pa.bias[0] = sa_bq; pa.dst[0] = Qh;  pa.mode[0] = 2;
    pa.A[1] = XT;  pa.W[1] = WT[1]; pa.bias[1] = sa_bk; pa.dst[1] = Kh;  pa.mode[1] = 2;
    pa.A[2] = XT;  pa.W[2] = WT[2]; pa.bias[2] = sa_bv; pa.dst[2] = Vt;  pa.mode[2] = 5;
    pa.A[3] = CTT; pa.W[3] = WT[4]; pa.bias[3] = ca_bk; pa.dst[3] = Kh2; pa.mode[3] = 2;
    pa.A[4] = CTT; pa.W[4] = WT[5]; pa.bias[4] = ca_bv; pa.dst[4] = Vt2; pa.mode[4] = 5;
    kQKV<<<dim3(8, 16, 5), 128, SM82>>>(pa, nullptr, nullptr, nullptr, nullptr,
                                        0, 0, 0, 0, 0);

    // ---- self-attention ----
    kQK<<<dim3(8, 8, 32), 128, SM82>>>(pz, Qh, Kh, part, S, HDD, HDD, HDD, hs, hs);
    stat_combine_k<<<128, 256>>>((const float2*)part, (float2*)stat);
    pv_fused_k<<<dim3(1, 8, 32), 128, SMPV>>>(S, Vt, msum, (const float2*)stat, tmp);
    ln_res_k<<<NROWS, 256>>>(tmp, x, ln1_g, ln1_b, x1, x1t);

    // ---- cross-attention ----
    ProjArgs pq = {};
    pq.A[0] = x1t; pq.W[0] = WT[3]; pq.bias[0] = ca_bq; pq.dst[0] = Qh; pq.mode[0] = 2;
    kQKV<<<dim3(8, 16, 1), 128, SM82>>>(pq, nullptr, nullptr, nullptr, nullptr,
                                        0, 0, 0, 0, 0);
    kQK<<<dim3(8, 8, 32), 128, SM82>>>(pz, Qh, Kh2, part, S, HDD, HDD, HDD, hs, hs);
    stat_combine_k<<<128, 256>>>((const float2*)part, (float2*)stat);
    pv_fused_k<<<dim3(1, 8, 32), 128, SMPV>>>(S, Vt2, cpad, (const float2*)stat, tmp);
    ln_res_k<<<NROWS, 256>>>(tmp, x1, ln2_g, ln2_b, x2, x2t);

    // ---- MLP ----
    kRelu <<<dim3(8, 16, 1), 128, SM82>>>(pz, x2t, WT[6], mlp_b1, hid,
                                          EMB, EMB, EMB, 0, 0);
    kPlain<<<dim3(8, 16, 1), 128, SM82>>>(pz, hid, WT[7], mlp_b2, tmp,
                                          EMB, EMB, EMB, 0, 0);
    ln_res_k<<<NROWS, 256>>>(tmp, x2, ln3_g, ln3_b, out, nullptr);
}